// round 12
// baseline (speedup 1.0000x reference)
#include <cuda_runtime.h>
#include <cuda_bf16.h>
#include <cstdint>

// ---------------------------------------------------------------------------
// ComplementaryAttention  B=4 T=1024 D=512 H=8 hd=64   (round 11)
//   - scores v2: 128x64 CTA tile, 2 CTAs/SM (reg-capped), grid 4096
//   - av/gemm: __launch_bounds__(256,2) occupancy caps
// ---------------------------------------------------------------------------

#define NT 256

// fp32 scratch (floats)
#define OFF_FF  (10ull * 1024 * 1024)
#define OFF_GF  (12ull * 1024 * 1024)
#define OFF_FR  (14ull * 1024 * 1024)
#define OFF_GR  (16ull * 1024 * 1024)
#define OFF_MB  (18ull * 1024 * 1024)
#define OFF_ST  (22ull * 1024 * 1024)
#define OFF_CS  (22ull * 1024 * 1024 + 131072)
#define OFF_AT  (23ull * 1024 * 1024)

__device__ float g_scratch[56ull * 1024ull * 1024ull];

// bf16 scratch (elements)
#define BX_H   (0ull)
#define BX_L   (2ull  * 1024 * 1024)
#define BTF_H  (4ull  * 1024 * 1024)
#define BTF_L  (6ull  * 1024 * 1024)
#define BTR_H  (8ull  * 1024 * 1024)
#define BTR_L  (10ull * 1024 * 1024)
#define BW     (12ull * 1024 * 1024)
#define BQ_H   (16ull * 1024 * 1024)
#define BQ_L   (18ull * 1024 * 1024)
#define BK_H   (20ull * 1024 * 1024)
#define BK_L   (22ull * 1024 * 1024)
#define BV_H   (24ull * 1024 * 1024)
#define BV_L   (26ull * 1024 * 1024)
#define BT_H   (28ull * 1024 * 1024)
#define BT_L   (60ull * 1024 * 1024)

__device__ __nv_bfloat16 g_bfbuf[92ull * 1024ull * 1024ull];

// ---------------------------------------------------------------------------
// PTX helpers
// ---------------------------------------------------------------------------
__device__ __forceinline__ void mma16816(float* c, const uint32_t* a,
                                         const uint32_t* b) {
    asm volatile(
        "mma.sync.aligned.m16n8k16.row.col.f32.bf16.bf16.f32 "
        "{%0,%1,%2,%3}, {%4,%5,%6,%7}, {%8,%9}, {%0,%1,%2,%3};"
        : "+f"(c[0]), "+f"(c[1]), "+f"(c[2]), "+f"(c[3])
        : "r"(a[0]), "r"(a[1]), "r"(a[2]), "r"(a[3]), "r"(b[0]), "r"(b[1]));
}

#define LDSM4(r, addr) \
    asm volatile("ldmatrix.sync.aligned.m8n8.x4.shared.b16 {%0,%1,%2,%3}, [%4];" \
        : "=r"((r)[0]), "=r"((r)[1]), "=r"((r)[2]), "=r"((r)[3]) : "r"(addr))
#define LDSM4T(r, addr) \
    asm volatile("ldmatrix.sync.aligned.m8n8.x4.trans.shared.b16 {%0,%1,%2,%3}, [%4];" \
        : "=r"((r)[0]), "=r"((r)[1]), "=r"((r)[2]), "=r"((r)[3]) : "r"(addr))
#define STS128(addr, r0, r1, r2, r3) \
    asm volatile("st.shared.v4.b32 [%0], {%1,%2,%3,%4};" \
        :: "r"(addr), "r"(r0), "r"(r1), "r"(r2), "r"(r3))

__device__ __forceinline__ void cpa16(uint32_t d, const void* s) {
    asm volatile("cp.async.cg.shared.global [%0], [%1], 16;" :: "r"(d), "l"(s));
}
#define CP_COMMIT() asm volatile("cp.async.commit_group;" ::: "memory")
#define CP_WAIT(n)  asm volatile("cp.async.wait_group %0;" :: "n"(n) : "memory")

#define ASTRIDE 72
#define A_ELEMS (128 * ASTRIDE)
#define B_ELEMS (64  * ASTRIDE)
#define STAGE_ELEMS (A_ELEMS + B_ELEMS)
#define HM_SMEM (2 * STAGE_ELEMS * 2)

// scores v2 smem (bytes)
#define SQH 0
#define SQL (A_ELEMS * 2)
#define SKH (2 * A_ELEMS * 2)
#define SKL (2 * A_ELEMS * 2 + B_ELEMS * 2)
#define SC_SMEM (2 * (A_ELEMS + B_ELEMS) * 2)   // 55296

// av smem tile offsets (elements within a stage)
#define AV_AFH 0
#define AV_AFL 4608
#define AV_ARH 9216
#define AV_ARL 13824
#define AV_VH  18432
#define AV_VL  23040
#define AV_STAGE 27648
#define AV_SMEM (2 * AV_STAGE * 2)

// ---------------------------------------------------------------------------
__device__ __forceinline__ void split2w(float v0, float v1,
                                        __nv_bfloat16* hp, __nv_bfloat16* lp) {
    __nv_bfloat16 h0 = __float2bfloat16(v0);
    __nv_bfloat16 h1 = __float2bfloat16(v1);
    __nv_bfloat162 hh; hh.x = h0; hh.y = h1;
    __nv_bfloat162 ll;
    ll.x = __float2bfloat16(v0 - __bfloat162float(h0));
    ll.y = __float2bfloat16(v1 - __bfloat162float(h1));
    *(__nv_bfloat162*)hp = hh;
    *(__nv_bfloat162*)lp = ll;
}
__device__ __forceinline__ void split4(const float* v,
                                       __nv_bfloat16* hp, __nv_bfloat16* lp) {
    split2w(v[0], v[1], hp, lp);
    split2w(v[2], v[3], hp + 2, lp + 2);
}

// ---------------------------------------------------------------------------
__global__ __launch_bounds__(NT)
void splitx_kernel(const float* __restrict__ x,
                   __nv_bfloat16* __restrict__ xh,
                   __nv_bfloat16* __restrict__ xl)
{
    const size_t i4 = (size_t)blockIdx.x * NT + threadIdx.x;
    float4 v = ((const float4*)x)[i4];
    float vv[4] = {v.x, v.y, v.z, v.w};
    split4(vv, xh + i4 * 4, xl + i4 * 4);
}

struct WPack { const float* w[7]; };

__global__ __launch_bounds__(NT)
void splitw_kernel(WPack p, __nv_bfloat16* __restrict__ base)
{
    const int wi = blockIdx.z;
    const float* W = p.w[wi];
    __nv_bfloat16* hO = base + (size_t)wi * 524288;
    __nv_bfloat16* lO = hO + 262144;
    __shared__ float t[32][33];
    const int n0 = blockIdx.x * 32, k0 = blockIdx.y * 32;
    const int lane = threadIdx.x & 31, ty = threadIdx.x >> 5;
#pragma unroll
    for (int p2 = 0; p2 < 4; ++p2) {
        int r = p2 * 8 + ty;
        t[r][lane] = W[(size_t)(k0 + r) * 512 + n0 + lane];
    }
    __syncthreads();
#pragma unroll
    for (int p2 = 0; p2 < 4; ++p2) {
        int r = p2 * 8 + ty;
        float v = t[lane][r];
        __nv_bfloat16 h = __float2bfloat16(v);
        __nv_bfloat16 l = __float2bfloat16(v - __bfloat162float(h));
        size_t o = (size_t)(n0 + r) * 512 + k0 + lane;
        hO[o] = h;
        lO[o] = l;
    }
}

// ---------------------------------------------------------------------------
// HMMA GEMM, z-indexed job pack.
// ---------------------------------------------------------------------------
struct GJob {
    const __nv_bfloat16 *Ah, *Al, *Bh, *Bl;
    const float* bias;
    float* C;
    __nv_bfloat16 *Ch, *Cl;
    int mode;
};
struct GJobs { GJob j[4]; };

__global__ __launch_bounds__(NT, 2)
void hmma_gemm_kernel(GJobs jobs)
{
    const GJob J = jobs.j[blockIdx.z];
    extern __shared__ __align__(16) __nv_bfloat16 smem[];
    const uint32_t smemU = (uint32_t)__cvta_generic_to_shared(smem);
    const int tid = threadIdx.x, lane = tid & 31, wid = tid >> 5;
    const int m0 = blockIdx.y * 128, n0 = blockIdx.x * 64;
    const int wm = (wid & 3) * 32, wn = (wid >> 2) * 32;
    const int arow = tid >> 1, ahof = (tid & 1) * 32;
    const int brow = tid >> 2, bqof = (tid & 3) * 16;

    auto load_chunk = [&](int c, int buf) {
        const int phase = c >> 3, kc = (c & 7) << 6;
        const __nv_bfloat16* As = (phase == 1) ? J.Al : J.Ah;
        const __nv_bfloat16* Bs = (phase == 2) ? J.Bl : J.Bh;
        const uint32_t ab = smemU + buf * (STAGE_ELEMS * 2);
        const uint32_t bb = ab + A_ELEMS * 2;
        const __nv_bfloat16* as = As + (size_t)(m0 + arow) * 512 + kc + ahof;
        const uint32_t ad = ab + (arow * ASTRIDE + ahof) * 2;
#pragma unroll
        for (int i = 0; i < 4; ++i) cpa16(ad + i * 16, as + i * 8);
        const __nv_bfloat16* bs = Bs + (size_t)(n0 + brow) * 512 + kc + bqof;
        const uint32_t bd = bb + (brow * ASTRIDE + bqof) * 2;
#pragma unroll
        for (int i = 0; i < 2; ++i) cpa16(bd + i * 16, bs + i * 8);
        CP_COMMIT();
    };

    float acc[2][4][4] = {};
    const uint32_t aFrag =
        ((wm + (lane & 15)) * ASTRIDE + ((lane >> 4) & 1) * 8) * 2;
    const uint32_t bFrag =
        ((wn + (lane & 7) + ((lane >> 4) & 1) * 8) * ASTRIDE +
         ((lane >> 3) & 1) * 8) * 2;

    auto compute = [&](int buf) {
        const uint32_t ab = smemU + buf * (STAGE_ELEMS * 2);
        const uint32_t aA = ab + aFrag;
        const uint32_t bA = ab + A_ELEMS * 2 + bFrag;
        uint32_t fr[2][16];
        auto ldf = [&](int k16, uint32_t* f) {
            const uint32_t ko = k16 * 32;
            LDSM4(f, aA + ko);
            LDSM4(f + 4, aA + 16 * ASTRIDE * 2 + ko);
            LDSM4(f + 8, bA + ko);
            LDSM4(f + 12, bA + 16 * ASTRIDE * 2 + ko);
        };
        ldf(0, fr[0]);
#pragma unroll
        for (int k16 = 0; k16 < 4; ++k16) {
            if (k16 < 3) ldf(k16 + 1, fr[(k16 + 1) & 1]);
            uint32_t* f = fr[k16 & 1];
            mma16816(acc[0][0], f, f + 8);      mma16816(acc[0][1], f, f + 10);
            mma16816(acc[0][2], f, f + 12);     mma16816(acc[0][3], f, f + 14);
            mma16816(acc[1][0], f + 4, f + 8);  mma16816(acc[1][1], f + 4, f + 10);
            mma16816(acc[1][2], f + 4, f + 12); mma16816(acc[1][3], f + 4, f + 14);
        }
    };

    load_chunk(0, 0);
    for (int c = 0; c < 24; ++c) {
        if (c + 1 < 24) {
            load_chunk(c + 1, (c + 1) & 1);
            CP_WAIT(1);
        } else {
            CP_WAIT(0);
        }
        __syncthreads();
        compute(c & 1);
        __syncthreads();
    }

    const int g = lane >> 2, tg = (lane & 3) * 2;
#pragma unroll
    for (int mi = 0; mi < 2; ++mi) {
        const int r0 = m0 + wm + mi * 16 + g;
#pragma unroll
        for (int ni = 0; ni < 4; ++ni) {
            const int col = n0 + wn + ni * 8 + tg;
            const float b0v = J.bias[col], b1v = J.bias[col + 1];
            float v00 = acc[mi][ni][0] + b0v, v01 = acc[mi][ni][1] + b1v;
            float v10 = acc[mi][ni][2] + b0v, v11 = acc[mi][ni][3] + b1v;
            const size_t o0 = (size_t)r0 * 512 + col;
            const size_t o1 = (size_t)(r0 + 8) * 512 + col;
            if (J.mode == 0) {
                float2 lo = {v00, v01};
                float2 hi = {v10, v11};
                *(float2*)&J.C[o0] = lo;
                *(float2*)&J.C[o1] = hi;
            } else {
                split2w(v00, v01, J.Ch + o0, J.Cl + o0);
                split2w(v10, v11, J.Ch + o1, J.Cl + o1);
            }
        }
    }
}

// ---------------------------------------------------------------------------
// scores v2 (HMMA): per (b,h): At = 0.125 * (qh+ql)(kh+kl)^T
// CTA 128(q) x 64(k), warp tile 32x32, 2 CTAs/SM.
// ---------------------------------------------------------------------------
__global__ __launch_bounds__(NT, 2)
void scores_hmma_kernel(const __nv_bfloat16* __restrict__ qh,
                        const __nv_bfloat16* __restrict__ ql,
                        const __nv_bfloat16* __restrict__ kh,
                        const __nv_bfloat16* __restrict__ kl,
                        float* __restrict__ At)
{
    extern __shared__ __align__(16) __nv_bfloat16 smem[];
    const uint32_t smemU = (uint32_t)__cvta_generic_to_shared(smem);
    const int bh = blockIdx.z, b = bh >> 3, h = bh & 7;
    const int m0 = blockIdx.y * 128, n0 = blockIdx.x * 64;
    const int tid = threadIdx.x, lane = tid & 31, wid = tid >> 5;
    const int wm = (wid & 3) * 32, wn = (wid >> 2) * 32;

    const int qrow = tid >> 1, qoff = (tid & 1) * 32;
    const int krow = tid >> 2, koff = (tid & 3) * 16;
    const size_t qsrc = (size_t)(b * 1024 + m0 + qrow) * 512 + h * 64 + qoff;
    const size_t ksrc = (size_t)(b * 1024 + n0 + krow) * 512 + h * 64 + koff;
    const uint32_t qdst = (qrow * ASTRIDE + qoff) * 2;
    const uint32_t kdst = (krow * ASTRIDE + koff) * 2;
#pragma unroll
    for (int i = 0; i < 4; ++i) {
        cpa16(smemU + SQH + qdst + i * 16, qh + qsrc + i * 8);
        cpa16(smemU + SQL + qdst + i * 16, ql + qsrc + i * 8);
    }
#pragma unroll
    for (int i = 0; i < 2; ++i) {
        cpa16(smemU + SKH + kdst + i * 16, kh + ksrc + i * 8);
        cpa16(smemU + SKL + kdst + i * 16, kl + ksrc + i * 8);
    }
    CP_COMMIT();
    CP_WAIT(0);
    __syncthreads();

    float acc[2][4][4] = {};
    const uint32_t aFrag =
        ((wm + (lane & 15)) * ASTRIDE + ((lane >> 4) & 1) * 8) * 2;
    const uint32_t bFrag =
        ((wn + (lane & 7) + ((lane >> 4) & 1) * 8) * ASTRIDE +
         ((lane >> 3) & 1) * 8) * 2;

    const uint32_t aoffs[3] = {SQH, SQL, SQH};
    const uint32_t boffs[3] = {SKH, SKH, SKL};
#pragma unroll
    for (int pass = 0; pass < 3; ++pass) {
        const uint32_t aA = smemU + aoffs[pass] + aFrag;
        const uint32_t bA = smemU + boffs[pass] + bFrag;
        uint32_t fr[2][16];
        auto ldf = [&](int k16, uint32_t* f) {
            const uint32_t ko = k16 * 32;
            LDSM4(f, aA + ko);
            LDSM4(f + 4, aA + 16 * ASTRIDE * 2 + ko);
            LDSM4(f + 8, bA + ko);
            LDSM4(f + 12, bA + 16 * ASTRIDE * 2 + ko);
        };
        ldf(0, fr[0]);
#pragma unroll
        for (int k16 = 0; k16 < 4; ++k16) {
            if (k16 < 3) ldf(k16 + 1, fr[(k16 + 1) & 1]);
            uint32_t* f = fr[k16 & 1];
            mma16816(acc[0][0], f, f + 8);      mma16816(acc[0][1], f, f + 10);
            mma16816(acc[0][2], f, f + 12);     mma16816(acc[0][3], f, f + 14);
            mma16816(acc[1][0], f + 4, f + 8);  mma16816(acc[1][1], f + 4, f + 10);
            mma16816(acc[1][2], f + 4, f + 12); mma16816(acc[1][3], f + 4, f + 14);
        }
    }

    float* Cp = At + ((size_t)bh << 20);
    const int g = lane >> 2, tg = (lane & 3) * 2;
#pragma unroll
    for (int mi = 0; mi < 2; ++mi) {
        const int r0 = m0 + wm + mi * 16 + g;
#pragma unroll
        for (int ni = 0; ni < 4; ++ni) {
            const int col = n0 + wn + ni * 8 + tg;
            float2 lo = {acc[mi][ni][0] * 0.125f, acc[mi][ni][1] * 0.125f};
            float2 hi = {acc[mi][ni][2] * 0.125f, acc[mi][ni][3] * 0.125f};
            *(float2*)&Cp[(size_t)r0 * 1024 + col] = lo;
            *(float2*)&Cp[(size_t)(r0 + 8) * 1024 + col] = hi;
        }
    }
}

// ---------------------------------------------------------------------------
// fused softmax / z / masks / stats; emits (t-1) bf16 hi/lo planes
// ---------------------------------------------------------------------------
__device__ __forceinline__ float warpMaxF(float v) {
#pragma unroll
    for (int o = 16; o; o >>= 1) v = fmaxf(v, __shfl_xor_sync(0xffffffffu, v, o));
    return v;
}
__device__ __forceinline__ float warpSumF(float v) {
#pragma unroll
    for (int o = 16; o; o >>= 1) v += __shfl_xor_sync(0xffffffffu, v, o);
    return v;
}

__global__ __launch_bounds__(NT)
void fused_sm_kernel(const float* __restrict__ At,
                     const float* __restrict__ cw,
                     const float* __restrict__ cbp,
                     unsigned char* __restrict__ maskbuf,
                     float* __restrict__ stats,
                     __nv_bfloat16* __restrict__ tdh,
                     __nv_bfloat16* __restrict__ tdl)
{
    const int bq = blockIdx.x;
    const int b  = bq >> 10;
    const int q  = bq & 1023;
    const int tid  = threadIdx.x;
    const int lane = tid & 31, wid = tid >> 5;

    __shared__ float red[16][8];
    __shared__ float fin[16];

    const float cb = cbp[0];
    const size_t rowbase = ((size_t)q << 10) + (size_t)tid * 4;

    float a[8][4];
    float lm[8];
#pragma unroll
    for (int h = 0; h < 8; ++h) {
        float4 v = *(const float4*)(At + (size_t)(b * 8 + h) * 1048576 + rowbase);
        a[h][0] = v.x; a[h][1] = v.y; a[h][2] = v.z; a[h][3] = v.w;
        lm[h] = fmaxf(fmaxf(v.x, v.y), fmaxf(v.z, v.w));
    }
#pragma unroll
    for (int h = 0; h < 8; ++h) {
        float w = warpMaxF(lm[h]);
        if (lane == 0) red[h][wid] = w;
    }
    __syncthreads();
    if (tid < 8) {
        float m = red[tid][0];
#pragma unroll
        for (int i = 1; i < 8; ++i) m = fmaxf(m, red[tid][i]);
        fin[tid] = m;
    }
    __syncthreads();
    float ls[8];
#pragma unroll
    for (int h = 0; h < 8; ++h) {
        float m = fin[h];
        float s = 0.f;
#pragma unroll
        for (int j = 0; j < 4; ++j) {
            a[h][j] = __expf(a[h][j] - m);
            s += a[h][j];
        }
        ls[h] = s;
    }
    __syncthreads();
#pragma unroll
    for (int h = 0; h < 8; ++h) {
        float w = warpSumF(ls[h]);
        if (lane == 0) red[h][wid] = w;
    }
    __syncthreads();
    if (tid < 8) {
        float s = red[tid][0];
#pragma unroll
        for (int i = 1; i < 8; ++i) s += red[tid][i];
        fin[tid] = 1.0f / s;
    }
    __syncthreads();

    float zacc[4] = {cb, cb, cb, cb};
#pragma unroll
    for (int h = 0; h < 8; ++h) {
        float inv = fin[h];
        float w   = cw[h];
#pragma unroll
        for (int j = 0; j < 4; ++j) {
            a[h][j] *= inv;
            zacc[j] = fmaf(a[h][j], w, zacc[j]);
        }
    }
    unsigned mby[4];
#pragma unroll
    for (int j = 0; j < 4; ++j) {
        unsigned mf = (zacc[j] <= 0.f) ? 1u : 0u;
        unsigned mr = (zacc[j] >= 0.f) ? 2u : 0u;
        mby[j] = mf | mr;
    }

    float lsf[8], lsr[8];
#pragma unroll
    for (int h = 0; h < 8; ++h) {
        float sf = 0.f, sr = 0.f;
#pragma unroll
        for (int j = 0; j < 4; ++j) {
            float t = __expf(a[h][j]);
            a[h][j] = t;
            sf += (mby[j] & 1u) ? t : 1.0f;
            sr += (mby[j] & 2u) ? t : 1.0f;
        }
        lsf[h] = sf; lsr[h] = sr;
    }
    __syncthreads();
#pragma unroll
    for (int h = 0; h < 8; ++h) {
        float w = warpSumF(lsf[h]);
        if (lane == 0) red[h][wid] = w;
        w = warpSumF(lsr[h]);
        if (lane == 0) red[8 + h][wid] = w;
    }
    __syncthreads();
    if (tid < 16) {
        float s = red[tid][0];
#pragma unroll
        for (int i = 1; i < 8; ++i) s += red[tid][i];
        float inv = 1.0f / s;
        int h = tid & 7;
        int row = (b * 8 + h) * 1024 + q;
        if (tid < 8) stats[row] = inv;
        else         stats[32768 + row] = inv;
    }

#pragma unroll
    for (int h = 0; h < 8; ++h) {
        size_t o = (size_t)(b * 8 + h) * 1048576 + rowbase;
        split2w(a[h][0] - 1.0f, a[h][1] - 1.0f, tdh + o, tdl + o);
        split2w(a[h][2] - 1.0f, a[h][3] - 1.0f, tdh + o + 2, tdl + o + 2);
    }
    uchar4 m4 = {(unsigned char)mby[0], (unsigned char)mby[1],
                 (unsigned char)mby[2], (unsigned char)mby[3]};
    *(uchar4*)(maskbuf + (size_t)bq * 1024 + tid * 4) = m4;
}

// ---------------------------------------------------------------------------
// colsum[bh][d] = sum_k (vh+vl)[b,k,h*64+d]
// ---------------------------------------------------------------------------
__global__ __launch_bounds__(NT)
void colsum_kernel(const __nv_bfloat16* __restrict__ vh,
                   const __nv_bfloat16* __restrict__ vl,
                   float* __restrict__ cs)
{
    const int bh = blockIdx.x, b = bh >> 3, h = bh & 7;
    const int tid = threadIdx.x;
    const int d = tid & 63, part = tid >> 6;
    __shared__ float red[4][64];
    const __nv_bfloat16* p1 = vh + ((size_t)(b * 1024 + part * 256)) * 512 + h * 64 + d;
    const __nv_bfloat16* p2 = vl + ((size_t)(b * 1024 + part * 256)) * 512 + h * 64 + d;
    float s = 0.f;
    for (int k = 0; k < 256; ++k)
        s += __bfloat162float(p1[(size_t)k * 512]) + __bfloat162float(p2[(size_t)k * 512]);
    red[part][d] = s;
    __syncthreads();
    if (tid < 64)
        cs[bh * 64 + tid] = red[0][tid] + red[1][tid] + red[2][tid] + red[3][tid];
}

// ---------------------------------------------------------------------------
// av (HMMA): per (b,h), q-tile 64:
//   S_f[q][d] = sum_k (m_f ? (t-1) : 0)[q][k] * v[k][d]     (3 split passes)
//   T_f = (S_f + colsum)*rsf  -> bf16 hi/lo;   same for r branch.
// ---------------------------------------------------------------------------
__global__ __launch_bounds__(NT, 2)
void av_hmma_kernel(const __nv_bfloat16* __restrict__ tdh,
                    const __nv_bfloat16* __restrict__ tdl,
                    const unsigned char* __restrict__ maskb,
                    const float* __restrict__ stats,
                    const float* __restrict__ colsum,
                    const __nv_bfloat16* __restrict__ vh,
                    const __nv_bfloat16* __restrict__ vl,
                    __nv_bfloat16* __restrict__ Tfh, __nv_bfloat16* __restrict__ Tfl,
                    __nv_bfloat16* __restrict__ Trh, __nv_bfloat16* __restrict__ Trl)
{
    extern __shared__ __align__(16) __nv_bfloat16 smem[];
    const uint32_t smemU = (uint32_t)__cvta_generic_to_shared(smem);
    const int bh = blockIdx.y, b = bh >> 3, h = bh & 7;
    const int q0 = blockIdx.x * 64;
    const int tid = threadIdx.x, lane = tid & 31, wid = tid >> 5;
    const int branch = wid >> 2;
    const int wq = (wid & 3) * 16;

    const int row = tid >> 2, seg = (tid & 3) * 16;

    const __nv_bfloat16* thp = tdh + (size_t)bh * 1048576 + (size_t)(q0 + row) * 1024 + seg;
    const __nv_bfloat16* tlp = tdl + (size_t)bh * 1048576 + (size_t)(q0 + row) * 1024 + seg;
    const unsigned char* mp  = maskb + ((size_t)(b * 1024 + q0 + row)) * 1024 + seg;
    const __nv_bfloat16* vhp = vh + ((size_t)(b * 1024 + row)) * 512 + h * 64 + seg;
    const __nv_bfloat16* vlp = vl + ((size_t)(b * 1024 + row)) * 512 + h * 64 + seg;

    uint4 thR[2], tlR[2], mkR;
    auto loadA = [&](int c) {
        const int k0 = c * 64;
        thR[0] = *(const uint4*)(thp + k0);
        thR[1] = *(const uint4*)(thp + k0 + 8);
        tlR[0] = *(const uint4*)(tlp + k0);
        tlR[1] = *(const uint4*)(tlp + k0 + 8);
        mkR    = *(const uint4*)(mp + k0);
    };
    auto issueV = [&](int c, int buf) {
        const size_t ko = (size_t)c * 64 * 512;
        const uint32_t base = smemU + buf * (AV_STAGE * 2) + (row * ASTRIDE + seg) * 2;
        cpa16(base + AV_VH * 2,      vhp + ko);
        cpa16(base + AV_VH * 2 + 16, vhp + ko + 8);
        cpa16(base + AV_VL * 2,      vlp + ko);
        cpa16(base + AV_VL * 2 + 16, vlp + ko + 8);
        CP_COMMIT();
    };
    auto selstore = [&](int buf) {
        const uint32_t* thw = (const uint32_t*)thR;
        const uint32_t* tlw = (const uint32_t*)tlR;
        uint32_t mkw[4] = {mkR.x, mkR.y, mkR.z, mkR.w};
        uint32_t afh[8], afl[8], arh[8], arl[8];
#pragma unroll
        for (int i = 0; i < 8; ++i) {
            uint32_t mw = mkw[i >> 1];
            uint32_t sh = (i & 1) * 16;
            uint32_t m0 = (mw >> sh) & 0xFFu;
            uint32_t m1 = (mw >> (sh + 8)) & 0xFFu;
            uint32_t sF = ((m0 & 1u) ? 0x0000FFFFu : 0u) | ((m1 & 1u) ? 0xFFFF0000u : 0u);
            uint32_t sR = ((m0 & 2u) ? 0x0000FFFFu : 0u) | ((m1 & 2u) ? 0xFFFF0000u : 0u);
            afh[i] = thw[i] & sF;  arh[i] = thw[i] & sR;
            afl[i] = tlw[i] & sF;  arl[i] = tlw[i] & sR;
        }
        const uint32_t base = smemU + buf * (AV_STAGE * 2) + (row * ASTRIDE + seg) * 2;
        STS128(base + AV_AFH * 2,      afh[0], afh[1], afh[2], afh[3]);
        STS128(base + AV_AFH * 2 + 16, afh[4], afh[5], afh[6], afh[7]);
        STS128(base + AV_AFL * 2,      afl[0], afl[1], afl[2], afl[3]);
        STS128(base + AV_AFL * 2 + 16, afl[4], afl[5], afl[6], afl[7]);
        STS128(base + AV_ARH * 2,      arh[0], arh[1], arh[2], arh[3]);
        STS128(base + AV_ARH * 2 + 16, arh[4], arh[5], arh[6], arh[7]);
        STS128(base + AV_ARL * 2,      arl[0], arl[1], arl[2], arl[3]);
        STS128(base + AV_ARL * 2 + 16, arl[4], arl[5], arl[6], arl[7]);
    };

    float acc[8][4] = {};
    const uint32_t aOffH = (branch ? AV_ARH : AV_AFH) * 2 +
        ((wq + (lane & 15)) * ASTRIDE + ((lane >> 4) & 1) * 8) * 2;
    const uint32_t aOffL = (branch ? AV_ARL : AV_AFL) * 2 +
        ((wq + (lane & 15)) * ASTRIDE + ((lane >> 4) & 1) * 8) * 2;
    const uint32_t vLaneOff = ((lane & 15) * ASTRIDE + ((lane >> 4) & 1) * 8) * 2;

    auto compute = [&](int buf) {
        const uint32_t sb = smemU + buf * (AV_STAGE * 2);
#pragma unroll
        for (int k16 = 0; k16 < 4; ++k16) {
            uint32_t ah[4], al[4], fvh[16], fvl[16];
            LDSM4(ah, sb + aOffH + k16 * 32);
            LDSM4(al, sb + aOffL + k16 * 32);
            const uint32_t vkb = sb + vLaneOff + k16 * 16 * ASTRIDE * 2;
#pragma unroll
            for (int g = 0; g < 4; ++g) {
                LDSM4T(fvh + 4 * g, vkb + AV_VH * 2 + g * 32);
                LDSM4T(fvl + 4 * g, vkb + AV_VL * 2 + g * 32);
            }
#pragma unroll
            for (int n = 0; n < 8; ++n) {
                uint32_t* bh2 = fvh + 4 * (n >> 1) + 2 * (n & 1);
                uint32_t* bl2 = fvl + 4 * (n >> 1) + 2 * (n & 1);
                mma16816(acc[n], ah, bh2);
                mma16816(acc[n], ah, bl2);
                mma16816(acc[n], al, bh2);
            }
        }
    };

    loadA(0);
    issueV(0, 0);
    selstore(0);
    CP_WAIT(0);
    __syncthreads();

    for (int c = 0; c < 16; ++c) {
        const int cur = c & 1;
        const bool more = (c + 1) < 16;
        if (more) { issueV(c + 1, cur ^ 1); loadA(c + 1); }
        compute(cur);
        __syncthreads();
        if (more) {
            selstore(cur ^ 1);
            CP_WAIT(0);
            __syncthreads();
        }
    }

    const int g = lane >> 2, tg = (lane & 3) * 2;
    const int q1 = q0 + wq + g, q2 = q1 + 8;
    const int srow = (branch ? 32768 : 0) + bh * 1024;
    const float rs1 = stats[srow + q1];
    const float rs2 = stats[srow + q2];
    __nv_bfloat16* outH = branch ? Trh : Tfh;
    __nv_bfloat16* outL = branch ? Trl : Tfl;
#pragma unroll
    for (int n = 0; n < 8; ++n) {
        const int d = n * 8 + tg;
        const float cs0 = colsum[bh * 64 + d];
        const float cs1 = colsum[bh * 64 + d + 1];
        const size_t o1 = (size_t)(b * 1024 + q1) * 512 + h * 64 + d;
        const size_t o2 = (size_t)(b * 1024 + q2) * 512 + h * 64 + d;
        split2w((acc[n][0] + cs0) * rs1, (acc[n][1] + cs1) * rs1, outH + o1, outL + o1);
        split2w((acc[n][2] + cs0) * rs2, (acc[n][3] + cs1) * rs2, outH + o2, outL + o2);
    }
}

// ---------------------------------------------------------------------------
__global__ __launch_bounds__(NT)
void combine_kernel(const float* __restrict__ Ff, const float* __restrict__ Gf,
                    const float* __restrict__ Fr, const float* __restrict__ Gr,
                    float* __restrict__ out)
{
    const size_t i4 = (size_t)blockIdx.x * NT + threadIdx.x;
    float4 ff = ((const float4*)Ff)[i4];
    float4 gf = ((const float4*)Gf)[i4];
    float4 fr = ((const float4*)Fr)[i4];
    float4 gr = ((const float4*)Gr)[i4];

    float ffv[4] = {ff.x, ff.y, ff.z, ff.w};
    float gfv[4] = {gf.x, gf.y, gf.z, gf.w};
    float frv[4] = {fr.x, fr.y, fr.z, fr.w};
    float grv[4] = {gr.x, gr.y, gr.z, gr.w};
    float ov[4];
#pragma unroll
    for (int j = 0; j < 4; ++j) {
        float sgf = 1.0f / (1.0f + __expf(-gfv[j]));
        float sgr = 1.0f / (1.0f + __expf(-grv[j]));
        float w   = 1.0f / (1.0f + __expf(sgr - sgf));
        ov[j] = ffv[j] * w + frv[j] * (1.0f - w);
    }
    float4 o = {ov[0], ov[1], ov[2], ov[3]};
    ((float4*)out)[i4] = o;
}

// ---------------------------------------------------------------------------
extern "C" void kernel_launch(void* const* d_in, const int* in_sizes, int n_in,
                              void* d_out, int out_size)
{
    const float* x   = (const float*)d_in[0];
    const float* Wq  = (const float*)d_in[1];
    const float* bq  = (const float*)d_in[2];
    const float* Wk  = (const float*)d_in[3];
    const float* bk  = (const float*)d_in[4];
    const float* Wv  = (const float*)d_in[5];
    const float* bv  = (const float*)d_in[6];
    const float* cw  = (const float*)d_in[7];
    const float* cb  = (const float*)d_in[8];
    const float* Wfh = (const float*)d_in[9];
    const float* bfh = (const float*)d_in[10];
    const float* Wfg = (const float*)d_in[11];
    const float* bfg = (const float*)d_in[12];
    const float* Wrh = (const float*)d_in[13];
    const float* brh = (const float*)d_in[14];
    const float* Wrg = (const float*)d_in[15];
    const float* brg = (const float*)d_in[16];
    float* out = (float*)d_out;

    float* s = nullptr;
    cudaGetSymbolAddress((void**)&s, g_scratch);
    __nv_bfloat16* bb = nullptr;
    cudaGetSymbolAddress((void**)&bb, g_bfbuf);

    float* Ff    = s + OFF_FF;
    float* Gf    = s + OFF_GF;
    float* Fr    = s + OFF_FR;
    float* Gr    = s + OFF_GR;
    unsigned char* maskb = (unsigned char*)(s + OFF_MB);
    float* stats = s + OFF_ST;
    float* csum  = s + OFF_CS;
    float* At    = s + OFF_AT;

    __nv_bfloat16* xh  = bb + BX_H;
    __nv_bfloat16* xl  = bb + BX_L;
    __nv_bfloat16* tfh = bb + BTF_H;
    __nv_bfloat16* tfl = bb + BTF_L;
    __nv_bfloat16* trh = bb + BTR_H;
    __nv_bfloat16* trl = bb + BTR_L;
    __nv_bfloat16* wb  = bb + BW;
    __nv_bfloat16* qhb = bb + BQ_H;
    __nv_bfloat16* qlb = bb + BQ_L;
    __nv_bfloat16* khb = bb + BK_H;
    __nv_bfloat16* klb = bb + BK_L;
    __nv_bfloat16* vhb = bb + BV_H;
    __nv_bfloat16* vlb = bb + BV_L;
    __nv_bfloat16* tdh = bb + BT_H;
    __nv_bfloat16* tdl = bb + BT_L;

    cudaFuncSetAttribute(hmma_gemm_kernel,
                         cudaFuncAttributeMaxDynamicSharedMemorySize, HM_SMEM);
    cudaFuncSetAttribute(scores_hmma_kernel,
                         cudaFuncAttributeMaxDynamicSharedMemorySize, SC_SMEM);
    cudaFuncSetAttribute(av_hmma_kernel,
                         cudaFuncAttributeMaxDynamicSharedMemorySize, AV_SMEM);

    WPack wp;
    wp.w[0] = Wq;  wp.w[1] = Wk;  wp.w[2] = Wv;
    wp.w[3] = Wfh; wp.w[4] = Wfg; wp.w[5] = Wrh; wp.w[6] = Wrg;
    splitw_kernel<<<dim3(16, 16, 7), NT>>>(wp, wb);
    splitx_kernel<<<2048, NT>>>(x, xh, xl);

    GJobs qkv = {};
    qkv.j[0] = {xh, xl, wb + 0 * 524288, wb + 0 * 524288 + 262144, bq, nullptr, qhb, qlb, 1};
    qkv.j[1] = {xh, xl, wb + 1 * 524288, wb + 1 * 524288 + 262144, bk, nullptr, khb, klb, 1};
    qkv.j[2] = {xh, xl, wb + 2 * 524288, wb + 2 * 524288 + 262144, bv, nullptr, vhb, vlb, 1};
    hmma_gemm_kernel<<<dim3(8, 32, 3), NT, HM_SMEM>>>(qkv);

    scores_hmma_kernel<<<dim3(16, 8, 32), NT, SC_SMEM>>>(qhb, qlb, khb, klb, At);
    fused_sm_kernel<<<4096, NT>>>(At, cw, cb, maskb, stats, tdh, tdl);
    colsum_kernel<<<32, NT>>>(vhb, vlb, csum);
    av_hmma_kernel<<<dim3(16, 32), NT, AV_SMEM>>>(tdh, tdl, maskb, stats, csum,
                                                  vhb, vlb, tfh, tfl, trh, trl);

    GJobs fin = {};
    fin.j[0] = {tfh, tfl, wb + 3 * 524288, wb + 3 * 524288 + 262144, bfh, Ff, nullptr, nullptr, 0};
    fin.j[1] = {tfh, tfl, wb + 4 * 524288, wb + 4 * 524288 + 262144, bfg, Gf, nullptr, nullptr, 0};
    fin.j[2] = {trh, trl, wb + 5 * 524288, wb + 5 * 524288 + 262144, brh, Fr, nullptr, nullptr, 0};
    fin.j[3] = {trh, trl, wb + 6 * 524288, wb + 6 * 524288 + 262144, brg, Gr, nullptr, nullptr, 0};
    hmma_gemm_kernel<<<dim3(8, 32, 4), NT, HM_SMEM>>>(fin);

    combine_kernel<<<2048, NT>>>(Ff, Gf, Fr, Gr, out);
}

// round 13
// speedup vs baseline: 1.0567x; 1.0567x over previous
#include <cuda_runtime.h>
#include <cuda_bf16.h>
#include <cstdint>

// ---------------------------------------------------------------------------
// ComplementaryAttention  B=4 T=1024 D=512 H=8 hd=64   (round 13)
//   - scores v3: q-resident, k-streamed cp.async pipeline, 2 CTAs/SM
//   - av/gemm reverted to uncapped round-10 config
// ---------------------------------------------------------------------------

#define NT 256

// fp32 scratch (floats)
#define OFF_FF  (10ull * 1024 * 1024)
#define OFF_GF  (12ull * 1024 * 1024)
#define OFF_FR  (14ull * 1024 * 1024)
#define OFF_GR  (16ull * 1024 * 1024)
#define OFF_MB  (18ull * 1024 * 1024)
#define OFF_ST  (22ull * 1024 * 1024)
#define OFF_CS  (22ull * 1024 * 1024 + 131072)
#define OFF_AT  (23ull * 1024 * 1024)

__device__ float g_scratch[56ull * 1024ull * 1024ull];

// bf16 scratch (elements)
#define BX_H   (0ull)
#define BX_L   (2ull  * 1024 * 1024)
#define BTF_H  (4ull  * 1024 * 1024)
#define BTF_L  (6ull  * 1024 * 1024)
#define BTR_H  (8ull  * 1024 * 1024)
#define BTR_L  (10ull * 1024 * 1024)
#define BW     (12ull * 1024 * 1024)
#define BQ_H   (16ull * 1024 * 1024)
#define BQ_L   (18ull * 1024 * 1024)
#define BK_H   (20ull * 1024 * 1024)
#define BK_L   (22ull * 1024 * 1024)
#define BV_H   (24ull * 1024 * 1024)
#define BV_L   (26ull * 1024 * 1024)
#define BT_H   (28ull * 1024 * 1024)
#define BT_L   (60ull * 1024 * 1024)

__device__ __nv_bfloat16 g_bfbuf[92ull * 1024ull * 1024ull];

// ---------------------------------------------------------------------------
// PTX helpers
// ---------------------------------------------------------------------------
__device__ __forceinline__ void mma16816(float* c, const uint32_t* a,
                                         const uint32_t* b) {
    asm volatile(
        "mma.sync.aligned.m16n8k16.row.col.f32.bf16.bf16.f32 "
        "{%0,%1,%2,%3}, {%4,%5,%6,%7}, {%8,%9}, {%0,%1,%2,%3};"
        : "+f"(c[0]), "+f"(c[1]), "+f"(c[2]), "+f"(c[3])
        : "r"(a[0]), "r"(a[1]), "r"(a[2]), "r"(a[3]), "r"(b[0]), "r"(b[1]));
}

#define LDSM4(r, addr) \
    asm volatile("ldmatrix.sync.aligned.m8n8.x4.shared.b16 {%0,%1,%2,%3}, [%4];" \
        : "=r"((r)[0]), "=r"((r)[1]), "=r"((r)[2]), "=r"((r)[3]) : "r"(addr))
#define LDSM4T(r, addr) \
    asm volatile("ldmatrix.sync.aligned.m8n8.x4.trans.shared.b16 {%0,%1,%2,%3}, [%4];" \
        : "=r"((r)[0]), "=r"((r)[1]), "=r"((r)[2]), "=r"((r)[3]) : "r"(addr))
#define STS128(addr, r0, r1, r2, r3) \
    asm volatile("st.shared.v4.b32 [%0], {%1,%2,%3,%4};" \
        :: "r"(addr), "r"(r0), "r"(r1), "r"(r2), "r"(r3))

__device__ __forceinline__ void cpa16(uint32_t d, const void* s) {
    asm volatile("cp.async.cg.shared.global [%0], [%1], 16;" :: "r"(d), "l"(s));
}
#define CP_COMMIT() asm volatile("cp.async.commit_group;" ::: "memory")
#define CP_WAIT(n)  asm volatile("cp.async.wait_group %0;" :: "n"(n) : "memory")

#define ASTRIDE 72
#define A_ELEMS (128 * ASTRIDE)
#define B_ELEMS (64  * ASTRIDE)
#define STAGE_ELEMS (A_ELEMS + B_ELEMS)
#define HM_SMEM (2 * STAGE_ELEMS * 2)

// scores v3 smem (bytes): q tiles resident, k double-buffered
#define SCQ_H 0
#define SCQ_L 9216
#define SCK_BASE 18432
#define SCK_KL 18432                  // KL offset within a stage
#define SCK_STAGE 36864               // KH + KL
#define SC_SMEM (SCK_BASE + 2 * SCK_STAGE)   // 92160

// av smem tile offsets (elements within a stage)
#define AV_AFH 0
#define AV_AFL 4608
#define AV_ARH 9216
#define AV_ARL 13824
#define AV_VH  18432
#define AV_VL  23040
#define AV_STAGE 27648
#define AV_SMEM (2 * AV_STAGE * 2)

// ---------------------------------------------------------------------------
__device__ __forceinline__ void split2w(float v0, float v1,
                                        __nv_bfloat16* hp, __nv_bfloat16* lp) {
    __nv_bfloat16 h0 = __float2bfloat16(v0);
    __nv_bfloat16 h1 = __float2bfloat16(v1);
    __nv_bfloat162 hh; hh.x = h0; hh.y = h1;
    __nv_bfloat162 ll;
    ll.x = __float2bfloat16(v0 - __bfloat162float(h0));
    ll.y = __float2bfloat16(v1 - __bfloat162float(h1));
    *(__nv_bfloat162*)hp = hh;
    *(__nv_bfloat162*)lp = ll;
}
__device__ __forceinline__ void split4(const float* v,
                                       __nv_bfloat16* hp, __nv_bfloat16* lp) {
    split2w(v[0], v[1], hp, lp);
    split2w(v[2], v[3], hp + 2, lp + 2);
}

// ---------------------------------------------------------------------------
__global__ __launch_bounds__(NT)
void splitx_kernel(const float* __restrict__ x,
                   __nv_bfloat16* __restrict__ xh,
                   __nv_bfloat16* __restrict__ xl)
{
    const size_t i4 = (size_t)blockIdx.x * NT + threadIdx.x;
    float4 v = ((const float4*)x)[i4];
    float vv[4] = {v.x, v.y, v.z, v.w};
    split4(vv, xh + i4 * 4, xl + i4 * 4);
}

struct WPack { const float* w[7]; };

__global__ __launch_bounds__(NT)
void splitw_kernel(WPack p, __nv_bfloat16* __restrict__ base)
{
    const int wi = blockIdx.z;
    const float* W = p.w[wi];
    __nv_bfloat16* hO = base + (size_t)wi * 524288;
    __nv_bfloat16* lO = hO + 262144;
    __shared__ float t[32][33];
    const int n0 = blockIdx.x * 32, k0 = blockIdx.y * 32;
    const int lane = threadIdx.x & 31, ty = threadIdx.x >> 5;
#pragma unroll
    for (int p2 = 0; p2 < 4; ++p2) {
        int r = p2 * 8 + ty;
        t[r][lane] = W[(size_t)(k0 + r) * 512 + n0 + lane];
    }
    __syncthreads();
#pragma unroll
    for (int p2 = 0; p2 < 4; ++p2) {
        int r = p2 * 8 + ty;
        float v = t[lane][r];
        __nv_bfloat16 h = __float2bfloat16(v);
        __nv_bfloat16 l = __float2bfloat16(v - __bfloat162float(h));
        size_t o = (size_t)(n0 + r) * 512 + k0 + lane;
        hO[o] = h;
        lO[o] = l;
    }
}

// ---------------------------------------------------------------------------
// HMMA GEMM, z-indexed job pack.   (round-10 config, no occupancy cap)
// ---------------------------------------------------------------------------
struct GJob {
    const __nv_bfloat16 *Ah, *Al, *Bh, *Bl;
    const float* bias;
    float* C;
    __nv_bfloat16 *Ch, *Cl;
    int mode;
};
struct GJobs { GJob j[4]; };

__global__ __launch_bounds__(NT)
void hmma_gemm_kernel(GJobs jobs)
{
    const GJob J = jobs.j[blockIdx.z];
    extern __shared__ __align__(16) __nv_bfloat16 smem[];
    const uint32_t smemU = (uint32_t)__cvta_generic_to_shared(smem);
    const int tid = threadIdx.x, lane = tid & 31, wid = tid >> 5;
    const int m0 = blockIdx.y * 128, n0 = blockIdx.x * 64;
    const int wm = (wid & 3) * 32, wn = (wid >> 2) * 32;
    const int arow = tid >> 1, ahof = (tid & 1) * 32;
    const int brow = tid >> 2, bqof = (tid & 3) * 16;

    auto load_chunk = [&](int c, int buf) {
        const int phase = c >> 3, kc = (c & 7) << 6;
        const __nv_bfloat16* As = (phase == 1) ? J.Al : J.Ah;
        const __nv_bfloat16* Bs = (phase == 2) ? J.Bl : J.Bh;
        const uint32_t ab = smemU + buf * (STAGE_ELEMS * 2);
        const uint32_t bb = ab + A_ELEMS * 2;
        const __nv_bfloat16* as = As + (size_t)(m0 + arow) * 512 + kc + ahof;
        const uint32_t ad = ab + (arow * ASTRIDE + ahof) * 2;
#pragma unroll
        for (int i = 0; i < 4; ++i) cpa16(ad + i * 16, as + i * 8);
        const __nv_bfloat16* bs = Bs + (size_t)(n0 + brow) * 512 + kc + bqof;
        const uint32_t bd = bb + (brow * ASTRIDE + bqof) * 2;
#pragma unroll
        for (int i = 0; i < 2; ++i) cpa16(bd + i * 16, bs + i * 8);
        CP_COMMIT();
    };

    float acc[2][4][4] = {};
    const uint32_t aFrag =
        ((wm + (lane & 15)) * ASTRIDE + ((lane >> 4) & 1) * 8) * 2;
    const uint32_t bFrag =
        ((wn + (lane & 7) + ((lane >> 4) & 1) * 8) * ASTRIDE +
         ((lane >> 3) & 1) * 8) * 2;

    auto compute = [&](int buf) {
        const uint32_t ab = smemU + buf * (STAGE_ELEMS * 2);
        const uint32_t aA = ab + aFrag;
        const uint32_t bA = ab + A_ELEMS * 2 + bFrag;
        uint32_t fr[2][16];
        auto ldf = [&](int k16, uint32_t* f) {
            const uint32_t ko = k16 * 32;
            LDSM4(f, aA + ko);
            LDSM4(f + 4, aA + 16 * ASTRIDE * 2 + ko);
            LDSM4(f + 8, bA + ko);
            LDSM4(f + 12, bA + 16 * ASTRIDE * 2 + ko);
        };
        ldf(0, fr[0]);
#pragma unroll
        for (int k16 = 0; k16 < 4; ++k16) {
            if (k16 < 3) ldf(k16 + 1, fr[(k16 + 1) & 1]);
            uint32_t* f = fr[k16 & 1];
            mma16816(acc[0][0], f, f + 8);      mma16816(acc[0][1], f, f + 10);
            mma16816(acc[0][2], f, f + 12);     mma16816(acc[0][3], f, f + 14);
            mma16816(acc[1][0], f + 4, f + 8);  mma16816(acc[1][1], f + 4, f + 10);
            mma16816(acc[1][2], f + 4, f + 12); mma16816(acc[1][3], f + 4, f + 14);
        }
    };

    load_chunk(0, 0);
    for (int c = 0; c < 24; ++c) {
        if (c + 1 < 24) {
            load_chunk(c + 1, (c + 1) & 1);
            CP_WAIT(1);
        } else {
            CP_WAIT(0);
        }
        __syncthreads();
        compute(c & 1);
        __syncthreads();
    }

    const int g = lane >> 2, tg = (lane & 3) * 2;
#pragma unroll
    for (int mi = 0; mi < 2; ++mi) {
        const int r0 = m0 + wm + mi * 16 + g;
#pragma unroll
        for (int ni = 0; ni < 4; ++ni) {
            const int col = n0 + wn + ni * 8 + tg;
            const float b0v = J.bias[col], b1v = J.bias[col + 1];
            float v00 = acc[mi][ni][0] + b0v, v01 = acc[mi][ni][1] + b1v;
            float v10 = acc[mi][ni][2] + b0v, v11 = acc[mi][ni][3] + b1v;
            const size_t o0 = (size_t)r0 * 512 + col;
            const size_t o1 = (size_t)(r0 + 8) * 512 + col;
            if (J.mode == 0) {
                float2 lo = {v00, v01};
                float2 hi = {v10, v11};
                *(float2*)&J.C[o0] = lo;
                *(float2*)&J.C[o1] = hi;
            } else {
                split2w(v00, v01, J.Ch + o0, J.Cl + o0);
                split2w(v10, v11, J.Ch + o1, J.Cl + o1);
            }
        }
    }
}

// ---------------------------------------------------------------------------
// scores v3 (HMMA): per (b,h,q64): At = 0.125 * (qh+ql)(kh+kl)^T
// q hi/lo resident in smem; k streamed in 128-row chunks, double-buffered.
// 8 warps: 4(q16) x 2(k64).  acc 32 regs/thread -> 2 CTAs/SM.
// ---------------------------------------------------------------------------
__global__ __launch_bounds__(NT, 2)
void scores_hmma_kernel(const __nv_bfloat16* __restrict__ qh,
                        const __nv_bfloat16* __restrict__ ql,
                        const __nv_bfloat16* __restrict__ kh,
                        const __nv_bfloat16* __restrict__ kl,
                        float* __restrict__ At)
{
    extern __shared__ __align__(16) __nv_bfloat16 smem[];
    const uint32_t smemU = (uint32_t)__cvta_generic_to_shared(smem);
    const int bh = blockIdx.y, b = bh >> 3, h = bh & 7;
    const int q0 = blockIdx.x * 64;
    const int tid = threadIdx.x, lane = tid & 31, wid = tid >> 5;
    const int wm = (wid & 3) * 16, wn = (wid >> 2) * 64;

    // q loader: 64 rows x 64 cols, hi+lo (2 cpa16 each)
    const int qrow = tid >> 2, qseg = (tid & 3) * 16;
    const size_t qsrc = (size_t)(b * 1024 + q0 + qrow) * 512 + h * 64 + qseg;
    const uint32_t qdst = (qrow * ASTRIDE + qseg) * 2;
    cpa16(smemU + SCQ_H + qdst, qh + qsrc);
    cpa16(smemU + SCQ_H + qdst + 16, qh + qsrc + 8);
    cpa16(smemU + SCQ_L + qdst, ql + qsrc);
    cpa16(smemU + SCQ_L + qdst + 16, ql + qsrc + 8);

    // k loader: 128 rows x 64 cols per chunk, hi+lo (4 cpa16 each)
    const int krow = tid >> 1, kseg = (tid & 1) * 32;
    const uint32_t kdstOff = (krow * ASTRIDE + kseg) * 2;

    auto issueK = [&](int c, int buf) {
        const size_t ksrc = (size_t)(b * 1024 + c * 128 + krow) * 512 + h * 64 + kseg;
        const uint32_t kb = smemU + SCK_BASE + buf * SCK_STAGE + kdstOff;
#pragma unroll
        for (int i = 0; i < 4; ++i) cpa16(kb + i * 16, kh + ksrc + i * 8);
#pragma unroll
        for (int i = 0; i < 4; ++i) cpa16(kb + SCK_KL + i * 16, kl + ksrc + i * 8);
        CP_COMMIT();
    };

    const uint32_t aFragOff =
        ((wm + (lane & 15)) * ASTRIDE + ((lane >> 4) & 1) * 8) * 2;
    const uint32_t bFragOff =
        ((wn + (lane & 7) + ((lane >> 4) & 1) * 8) * ASTRIDE +
         ((lane >> 3) & 1) * 8) * 2;

    float* Cp = At + ((size_t)bh << 20);
    const int g = lane >> 2, tg = (lane & 3) * 2;

    issueK(0, 0);   // group 0 includes q (issued above) + k0

    for (int c = 0; c < 8; ++c) {
        if (c + 1 < 8) {
            issueK(c + 1, (c + 1) & 1);
            CP_WAIT(1);
        } else {
            CP_WAIT(0);
        }
        __syncthreads();

        float acc[8][4] = {};
        const uint32_t kbase = smemU + SCK_BASE + (c & 1) * SCK_STAGE;
#pragma unroll
        for (int pass = 0; pass < 3; ++pass) {
            const uint32_t aA = smemU + (pass == 1 ? SCQ_L : SCQ_H) + aFragOff;
            const uint32_t bA = kbase + (pass == 2 ? SCK_KL : 0) + bFragOff;
#pragma unroll
            for (int k16 = 0; k16 < 4; ++k16) {
                const uint32_t ko = k16 * 32;
                uint32_t a[4];
                LDSM4(a, aA + ko);
                uint32_t bf[4][4];
#pragma unroll
                for (int nj = 0; nj < 4; ++nj)
                    LDSM4(bf[nj], bA + nj * 16 * ASTRIDE * 2 + ko);
#pragma unroll
                for (int nj = 0; nj < 4; ++nj) {
                    mma16816(acc[2 * nj],     a, bf[nj]);
                    mma16816(acc[2 * nj + 1], a, bf[nj] + 2);
                }
            }
        }

        // write 64 x 128 tile for this chunk
        const int r0 = q0 + wm + g;
#pragma unroll
        for (int ni = 0; ni < 8; ++ni) {
            const int col = c * 128 + wn + ni * 8 + tg;
            float2 lo = {acc[ni][0] * 0.125f, acc[ni][1] * 0.125f};
            float2 hi = {acc[ni][2] * 0.125f, acc[ni][3] * 0.125f};
            *(float2*)&Cp[(size_t)r0 * 1024 + col] = lo;
            *(float2*)&Cp[(size_t)(r0 + 8) * 1024 + col] = hi;
        }
        __syncthreads();
    }
}

// ---------------------------------------------------------------------------
// fused softmax / z / masks / stats; emits (t-1) bf16 hi/lo planes
// ---------------------------------------------------------------------------
__device__ __forceinline__ float warpMaxF(float v) {
#pragma unroll
    for (int o = 16; o; o >>= 1) v = fmaxf(v, __shfl_xor_sync(0xffffffffu, v, o));
    return v;
}
__device__ __forceinline__ float warpSumF(float v) {
#pragma unroll
    for (int o = 16; o; o >>= 1) v += __shfl_xor_sync(0xffffffffu, v, o);
    return v;
}

__global__ __launch_bounds__(NT)
void fused_sm_kernel(const float* __restrict__ At,
                     const float* __restrict__ cw,
                     const float* __restrict__ cbp,
                     unsigned char* __restrict__ maskbuf,
                     float* __restrict__ stats,
                     __nv_bfloat16* __restrict__ tdh,
                     __nv_bfloat16* __restrict__ tdl)
{
    const int bq = blockIdx.x;
    const int b  = bq >> 10;
    const int q  = bq & 1023;
    const int tid  = threadIdx.x;
    const int lane = tid & 31, wid = tid >> 5;

    __shared__ float red[16][8];
    __shared__ float fin[16];

    const float cb = cbp[0];
    const size_t rowbase = ((size_t)q << 10) + (size_t)tid * 4;

    float a[8][4];
    float lm[8];
#pragma unroll
    for (int h = 0; h < 8; ++h) {
        float4 v = *(const float4*)(At + (size_t)(b * 8 + h) * 1048576 + rowbase);
        a[h][0] = v.x; a[h][1] = v.y; a[h][2] = v.z; a[h][3] = v.w;
        lm[h] = fmaxf(fmaxf(v.x, v.y), fmaxf(v.z, v.w));
    }
#pragma unroll
    for (int h = 0; h < 8; ++h) {
        float w = warpMaxF(lm[h]);
        if (lane == 0) red[h][wid] = w;
    }
    __syncthreads();
    if (tid < 8) {
        float m = red[tid][0];
#pragma unroll
        for (int i = 1; i < 8; ++i) m = fmaxf(m, red[tid][i]);
        fin[tid] = m;
    }
    __syncthreads();
    float ls[8];
#pragma unroll
    for (int h = 0; h < 8; ++h) {
        float m = fin[h];
        float s = 0.f;
#pragma unroll
        for (int j = 0; j < 4; ++j) {
            a[h][j] = __expf(a[h][j] - m);
            s += a[h][j];
        }
        ls[h] = s;
    }
    __syncthreads();
#pragma unroll
    for (int h = 0; h < 8; ++h) {
        float w = warpSumF(ls[h]);
        if (lane == 0) red[h][wid] = w;
    }
    __syncthreads();
    if (tid < 8) {
        float s = red[tid][0];
#pragma unroll
        for (int i = 1; i < 8; ++i) s += red[tid][i];
        fin[tid] = 1.0f / s;
    }
    __syncthreads();

    float zacc[4] = {cb, cb, cb, cb};
#pragma unroll
    for (int h = 0; h < 8; ++h) {
        float inv = fin[h];
        float w   = cw[h];
#pragma unroll
        for (int j = 0; j < 4; ++j) {
            a[h][j] *= inv;
            zacc[j] = fmaf(a[h][j], w, zacc[j]);
        }
    }
    unsigned mby[4];
#pragma unroll
    for (int j = 0; j < 4; ++j) {
        unsigned mf = (zacc[j] <= 0.f) ? 1u : 0u;
        unsigned mr = (zacc[j] >= 0.f) ? 2u : 0u;
        mby[j] = mf | mr;
    }

    float lsf[8], lsr[8];
#pragma unroll
    for (int h = 0; h < 8; ++h) {
        float sf = 0.f, sr = 0.f;
#pragma unroll
        for (int j = 0; j < 4; ++j) {
            float t = __expf(a[h][j]);
            a[h][j] = t;
            sf += (mby[j] & 1u) ? t : 1.0f;
            sr += (mby[j] & 2u) ? t : 1.0f;
        }
        lsf[h] = sf; lsr[h] = sr;
    }
    __syncthreads();
#pragma unroll
    for (int h = 0; h < 8; ++h) {
        float w = warpSumF(lsf[h]);
        if (lane == 0) red[h][wid] = w;
        w = warpSumF(lsr[h]);
        if (lane == 0) red[8 + h][wid] = w;
    }
    __syncthreads();
    if (tid < 16) {
        float s = red[tid][0];
#pragma unroll
        for (int i = 1; i < 8; ++i) s += red[tid][i];
        float inv = 1.0f / s;
        int h = tid & 7;
        int row = (b * 8 + h) * 1024 + q;
        if (tid < 8) stats[row] = inv;
        else         stats[32768 + row] = inv;
    }

#pragma unroll
    for (int h = 0; h < 8; ++h) {
        size_t o = (size_t)(b * 8 + h) * 1048576 + rowbase;
        split2w(a[h][0] - 1.0f, a[h][1] - 1.0f, tdh + o, tdl + o);
        split2w(a[h][2] - 1.0f, a[h][3] - 1.0f, tdh + o + 2, tdl + o + 2);
    }
    uchar4 m4 = {(unsigned char)mby[0], (unsigned char)mby[1],
                 (unsigned char)mby[2], (unsigned char)mby[3]};
    *(uchar4*)(maskbuf + (size_t)bq * 1024 + tid * 4) = m4;
}

// ---------------------------------------------------------------------------
// colsum[bh][d] = sum_k (vh+vl)[b,k,h*64+d]
// ---------------------------------------------------------------------------
__global__ __launch_bounds__(NT)
void colsum_kernel(const __nv_bfloat16* __restrict__ vh,
                   const __nv_bfloat16* __restrict__ vl,
                   float* __restrict__ cs)
{
    const int bh = blockIdx.x, b = bh >> 3, h = bh & 7;
    const int tid = threadIdx.x;
    const int d = tid & 63, part = tid >> 6;
    __shared__ float red[4][64];
    const __nv_bfloat16* p1 = vh + ((size_t)(b * 1024 + part * 256)) * 512 + h * 64 + d;
    const __nv_bfloat16* p2 = vl + ((size_t)(b * 1024 + part * 256)) * 512 + h * 64 + d;
    float s = 0.f;
    for (int k = 0; k < 256; ++k)
        s += __bfloat162float(p1[(size_t)k * 512]) + __bfloat162float(p2[(size_t)k * 512]);
    red[part][d] = s;
    __syncthreads();
    if (tid < 64)
        cs[bh * 64 + tid] = red[0][tid] + red[1][tid] + red[2][tid] + red[3][tid];
}

// ---------------------------------------------------------------------------
// av (HMMA): per (b,h), q-tile 64  (round-10 config, no occupancy cap)
// ---------------------------------------------------------------------------
__global__ __launch_bounds__(NT)
void av_hmma_kernel(const __nv_bfloat16* __restrict__ tdh,
                    const __nv_bfloat16* __restrict__ tdl,
                    const unsigned char* __restrict__ maskb,
                    const float* __restrict__ stats,
                    const float* __restrict__ colsum,
                    const __nv_bfloat16* __restrict__ vh,
                    const __nv_bfloat16* __restrict__ vl,
                    __nv_bfloat16* __restrict__ Tfh, __nv_bfloat16* __restrict__ Tfl,
                    __nv_bfloat16* __restrict__ Trh, __nv_bfloat16* __restrict__ Trl)
{
    extern __shared__ __align__(16) __nv_bfloat16 smem[];
    const uint32_t smemU = (uint32_t)__cvta_generic_to_shared(smem);
    const int bh = blockIdx.y, b = bh >> 3, h = bh & 7;
    const int q0 = blockIdx.x * 64;
    const int tid = threadIdx.x, lane = tid & 31, wid = tid >> 5;
    const int branch = wid >> 2;
    const int wq = (wid & 3) * 16;

    const int row = tid >> 2, seg = (tid & 3) * 16;

    const __nv_bfloat16* thp = tdh + (size_t)bh * 1048576 + (size_t)(q0 + row) * 1024 + seg;
    const __nv_bfloat16* tlp = tdl + (size_t)bh * 1048576 + (size_t)(q0 + row) * 1024 + seg;
    const unsigned char* mp  = maskb + ((size_t)(b * 1024 + q0 + row)) * 1024 + seg;
    const __nv_bfloat16* vhp = vh + ((size_t)(b * 1024 + row)) * 512 + h * 64 + seg;
    const __nv_bfloat16* vlp = vl + ((size_t)(b * 1024 + row)) * 512 + h * 64 + seg;

    uint4 thR[2], tlR[2], mkR;
    auto loadA = [&](int c) {
        const int k0 = c * 64;
        thR[0] = *(const uint4*)(thp + k0);
        thR[1] = *(const uint4*)(thp + k0 + 8);
        tlR[0] = *(const uint4*)(tlp + k0);
        tlR[1] = *(const uint4*)(tlp + k0 + 8);
        mkR    = *(const uint4*)(mp + k0);
    };
    auto issueV = [&](int c, int buf) {
        const size_t ko = (size_t)c * 64 * 512;
        const uint32_t base = smemU + buf * (AV_STAGE * 2) + (row * ASTRIDE + seg) * 2;
        cpa16(base + AV_VH * 2,      vhp + ko);
        cpa16(base + AV_VH * 2 + 16, vhp + ko + 8);
        cpa16(base + AV_VL * 2,      vlp + ko);
        cpa16(base + AV_VL * 2 + 16, vlp + ko + 8);
        CP_COMMIT();
    };
    auto selstore = [&](int buf) {
        const uint32_t* thw = (const uint32_t*)thR;
        const uint32_t* tlw = (const uint32_t*)tlR;
        uint32_t mkw[4] = {mkR.x, mkR.y, mkR.z, mkR.w};
        uint32_t afh[8], afl[8], arh[8], arl[8];
#pragma unroll
        for (int i = 0; i < 8; ++i) {
            uint32_t mw = mkw[i >> 1];
            uint32_t sh = (i & 1) * 16;
            uint32_t m0 = (mw >> sh) & 0xFFu;
            uint32_t m1 = (mw >> (sh + 8)) & 0xFFu;
            uint32_t sF = ((m0 & 1u) ? 0x0000FFFFu : 0u) | ((m1 & 1u) ? 0xFFFF0000u : 0u);
            uint32_t sR = ((m0 & 2u) ? 0x0000FFFFu : 0u) | ((m1 & 2u) ? 0xFFFF0000u : 0u);
            afh[i] = thw[i] & sF;  arh[i] = thw[i] & sR;
            afl[i] = tlw[i] & sF;  arl[i] = tlw[i] & sR;
        }
        const uint32_t base = smemU + buf * (AV_STAGE * 2) + (row * ASTRIDE + seg) * 2;
        STS128(base + AV_AFH * 2,      afh[0], afh[1], afh[2], afh[3]);
        STS128(base + AV_AFH * 2 + 16, afh[4], afh[5], afh[6], afh[7]);
        STS128(base + AV_AFL * 2,      afl[0], afl[1], afl[2], afl[3]);
        STS128(base + AV_AFL * 2 + 16, afl[4], afl[5], afl[6], afl[7]);
        STS128(base + AV_ARH * 2,      arh[0], arh[1], arh[2], arh[3]);
        STS128(base + AV_ARH * 2 + 16, arh[4], arh[5], arh[6], arh[7]);
        STS128(base + AV_ARL * 2,      arl[0], arl[1], arl[2], arl[3]);
        STS128(base + AV_ARL * 2 + 16, arl[4], arl[5], arl[6], arl[7]);
    };

    float acc[8][4] = {};
    const uint32_t aOffH = (branch ? AV_ARH : AV_AFH) * 2 +
        ((wq + (lane & 15)) * ASTRIDE + ((lane >> 4) & 1) * 8) * 2;
    const uint32_t aOffL = (branch ? AV_ARL : AV_AFL) * 2 +
        ((wq + (lane & 15)) * ASTRIDE + ((lane >> 4) & 1) * 8) * 2;
    const uint32_t vLaneOff = ((lane & 15) * ASTRIDE + ((lane >> 4) & 1) * 8) * 2;

    auto compute = [&](int buf) {
        const uint32_t sb = smemU + buf * (AV_STAGE * 2);
#pragma unroll
        for (int k16 = 0; k16 < 4; ++k16) {
            uint32_t ah[4], al[4], fvh[16], fvl[16];
            LDSM4(ah, sb + aOffH + k16 * 32);
            LDSM4(al, sb + aOffL + k16 * 32);
            const uint32_t vkb = sb + vLaneOff + k16 * 16 * ASTRIDE * 2;
#pragma unroll
            for (int g = 0; g < 4; ++g) {
                LDSM4T(fvh + 4 * g, vkb + AV_VH * 2 + g * 32);
                LDSM4T(fvl + 4 * g, vkb + AV_VL * 2 + g * 32);
            }
#pragma unroll
            for (int n = 0; n < 8; ++n) {
                uint32_t* bh2 = fvh + 4 * (n >> 1) + 2 * (n & 1);
                uint32_t* bl2 = fvl + 4 * (n >> 1) + 2 * (n & 1);
                mma16816(acc[n], ah, bh2);
                mma16816(acc[n], ah, bl2);
                mma16816(acc[n], al, bh2);
            }
        }
    };

    loadA(0);
    issueV(0, 0);
    selstore(0);
    CP_WAIT(0);
    __syncthreads();

    for (int c = 0; c < 16; ++c) {
        const int cur = c & 1;
        const bool more = (c + 1) < 16;
        if (more) { issueV(c + 1, cur ^ 1); loadA(c + 1); }
        compute(cur);
        __syncthreads();
        if (more) {
            selstore(cur ^ 1);
            CP_WAIT(0);
            __syncthreads();
        }
    }

    const int g = lane >> 2, tg = (lane & 3) * 2;
    const int q1 = q0 + wq + g, q2 = q1 + 8;
    const int srow = (branch ? 32768 : 0) + bh * 1024;
    const float rs1 = stats[srow + q1];
    const float rs2 = stats[srow + q2];
    __nv_bfloat16* outH = branch ? Trh : Tfh;
    __nv_bfloat16* outL = branch ? Trl : Tfl;
#pragma unroll
    for (int n = 0; n < 8; ++n) {
        const int d = n * 8 + tg;
        const float cs0 = colsum[bh * 64 + d];
        const float cs1 = colsum[bh * 64 + d + 1];
        const size_t o1 = (size_t)(b * 1024 + q1) * 512 + h * 64 + d;
        const size_t o2 = (size_t)(b * 1024 + q2) * 512 + h * 64 + d;
        split2w((acc[n][0] + cs0) * rs1, (acc[n][1] + cs1) * rs1, outH + o1, outL + o1);
        split2w((acc[n][2] + cs0) * rs2, (acc[n][3] + cs1) * rs2, outH + o2, outL + o2);
    }
}

// ---------------------------------------------------------------------------
__global__ __launch_bounds__(NT)
void combine_kernel(const float* __restrict__ Ff, const float* __restrict__ Gf,
                    const float* __restrict__ Fr, const float* __restrict__ Gr,
                    float* __restrict__ out)
{
    const size_t i4 = (size_t)blockIdx.x * NT + threadIdx.x;
    float4 ff = ((const float4*)Ff)[i4];
    float4 gf = ((const float4*)Gf)[i4];
    float4 fr = ((const float4*)Fr)[i4];
    float4 gr = ((const float4*)Gr)[i4];

    float ffv[4] = {ff.x, ff.y, ff.z, ff.w};
    float gfv[4] = {gf.x, gf.y, gf.z, gf.w};
    float frv[4] = {fr.x, fr.y, fr.z, fr.w};
    float grv[4] = {gr.x, gr.y, gr.z, gr.w};
    float ov[4];
#pragma unroll
    for (int j = 0; j < 4; ++j) {
        float sgf = 1.0f / (1.0f + __expf(-gfv[j]));
        float sgr = 1.0f / (1.0f + __expf(-grv[j]));
        float w   = 1.0f / (1.0f + __expf(sgr - sgf));
        ov[j] = ffv[j] * w + frv[j] * (1.0f - w);
    }
    float4 o = {ov[0], ov[1], ov[2], ov[3]};
    ((float4*)out)[i4] = o;
}

// ---------------------------------------------------------------------------
extern "C" void kernel_launch(void* const* d_in, const int* in_sizes, int n_in,
                              void* d_out, int out_size)
{
    const float* x   = (const float*)d_in[0];
    const float* Wq  = (const float*)d_in[1];
    const float* bq  = (const float*)d_in[2];
    const float* Wk  = (const float*)d_in[3];
    const float* bk  = (const float*)d_in[4];
    const float* Wv  = (const float*)d_in[5];
    const float* bv  = (const float*)d_in[6];
    const float* cw  = (const float*)d_in[7];
    const float* cb  = (const float*)d_in[8];
    const float* Wfh = (const float*)d_in[9];
    const float* bfh = (const float*)d_in[10];
    const float* Wfg = (const float*)d_in[11];
    const float* bfg = (const float*)d_in[12];
    const float* Wrh = (const float*)d_in[13];
    const float* brh = (const float*)d_in[14];
    const float* Wrg = (const float*)d_in[15];
    const float* brg = (const float*)d_in[16];
    float* out = (float*)d_out;

    float* s = nullptr;
    cudaGetSymbolAddress((void**)&s, g_scratch);
    __nv_bfloat16* bb = nullptr;
    cudaGetSymbolAddress((void**)&bb, g_bfbuf);

    float* Ff    = s + OFF_FF;
    float* Gf    = s + OFF_GF;
    float* Fr    = s + OFF_FR;
    float* Gr    = s + OFF_GR;
    unsigned char* maskb = (unsigned char*)(s + OFF_MB);
    float* stats = s + OFF_ST;
    float* csum  = s + OFF_CS;
    float* At    = s + OFF_AT;

    __nv_bfloat16* xh  = bb + BX_H;
    __nv_bfloat16* xl  = bb + BX_L;
    __nv_bfloat16* tfh = bb + BTF_H;
    __nv_bfloat16* tfl = bb + BTF_L;
    __nv_bfloat16* trh = bb + BTR_H;
    __nv_bfloat16* trl = bb + BTR_L;
    __nv_bfloat16* wb  = bb + BW;
    __nv_bfloat16* qhb = bb + BQ_H;
    __nv_bfloat16* qlb = bb + BQ_L;
    __nv_bfloat16* khb = bb + BK_H;
    __nv_bfloat16* klb = bb + BK_L;
    __nv_bfloat16* vhb = bb + BV_H;
    __nv_bfloat16* vlb = bb + BV_L;
    __nv_bfloat16* tdh = bb + BT_H;
    __nv_bfloat16* tdl = bb + BT_L;

    cudaFuncSetAttribute(hmma_gemm_kernel,
                         cudaFuncAttributeMaxDynamicSharedMemorySize, HM_SMEM);
    cudaFuncSetAttribute(scores_hmma_kernel,
                         cudaFuncAttributeMaxDynamicSharedMemorySize, SC_SMEM);
    cudaFuncSetAttribute(av_hmma_kernel,
                         cudaFuncAttributeMaxDynamicSharedMemorySize, AV_SMEM);

    WPack wp;
    wp.w[0] = Wq;  wp.w[1] = Wk;  wp.w[2] = Wv;
    wp.w[3] = Wfh; wp.w[4] = Wfg; wp.w[5] = Wrh; wp.w[6] = Wrg;
    splitw_kernel<<<dim3(16, 16, 7), NT>>>(wp, wb);
    splitx_kernel<<<2048, NT>>>(x, xh, xl);

    GJobs qkv = {};
    qkv.j[0] = {xh, xl, wb + 0 * 524288, wb + 0 * 524288 + 262144, bq, nullptr, qhb, qlb, 1};
    qkv.j[1] = {xh, xl, wb + 1 * 524288, wb + 1 * 524288 + 262144, bk, nullptr, khb, klb, 1};
    qkv.j[2] = {xh, xl, wb + 2 * 524288, wb + 2 * 524288 + 262144, bv, nullptr, vhb, vlb, 1};
    hmma_gemm_kernel<<<dim3(8, 32, 3), NT, HM_SMEM>>>(qkv);

    scores_hmma_kernel<<<dim3(16, 32), NT, SC_SMEM>>>(qhb, qlb, khb, klb, At);
    fused_sm_kernel<<<4096, NT>>>(At, cw, cb, maskb, stats, tdh, tdl);
    colsum_kernel<<<32, NT>>>(vhb, vlb, csum);
    av_hmma_kernel<<<dim3(16, 32), NT, AV_SMEM>>>(tdh, tdl, maskb, stats, csum,
                                                  vhb, vlb, tfh, tfl, trh, trl);

    GJobs fin = {};
    fin.j[0] = {tfh, tfl, wb + 3 * 524288, wb + 3 * 524288 + 262144, bfh, Ff, nullptr, nullptr, 0};
    fin.j[1] = {tfh, tfl, wb + 4 * 524288, wb + 4 * 524288 + 262144, bfg, Gf, nullptr, nullptr, 0};
    fin.j[2] = {trh, trl, wb + 5 * 524288, wb + 5 * 524288 + 262144, brh, Fr, nullptr, nullptr, 0};
    fin.j[3] = {trh, trl, wb + 6 * 524288, wb + 6 * 524288 + 262144, brg, Gr, nullptr, nullptr, 0};
    hmma_gemm_kernel<<<dim3(8, 32, 4), NT, HM_SMEM>>>(fin);

    combine_kernel<<<2048, NT>>>(Ff, Gf, Fr, Gr, out);
}

// round 16
// speedup vs baseline: 1.0645x; 1.0074x over previous
#include <cuda_runtime.h>
#include <cuda_bf16.h>
#include <cuda_fp16.h>
#include <cstdint>

// ---------------------------------------------------------------------------
// ComplementaryAttention  B=4 T=1024 D=512 H=8 hd=64   (round 14)
//   - scores v4: frag-shared 3-pass inner loop (10 LDSM4 / 24 MMA), fp16 At
//   - fused_sm reads fp16 At
//   - av/gemm unchanged (round-13 validated config)
// ---------------------------------------------------------------------------

#define NT 256

// fp32 scratch (floats)
#define OFF_FF  (10ull * 1024 * 1024)
#define OFF_GF  (12ull * 1024 * 1024)
#define OFF_FR  (14ull * 1024 * 1024)
#define OFF_GR  (16ull * 1024 * 1024)
#define OFF_MB  (18ull * 1024 * 1024)
#define OFF_ST  (22ull * 1024 * 1024)
#define OFF_CS  (22ull * 1024 * 1024 + 131072)
#define OFF_AT  (23ull * 1024 * 1024)   // reused as __half buffer (32M halves)

__device__ float g_scratch[56ull * 1024ull * 1024ull];

// bf16 scratch (elements)
#define BX_H   (0ull)
#define BX_L   (2ull  * 1024 * 1024)
#define BTF_H  (4ull  * 1024 * 1024)
#define BTF_L  (6ull  * 1024 * 1024)
#define BTR_H  (8ull  * 1024 * 1024)
#define BTR_L  (10ull * 1024 * 1024)
#define BW     (12ull * 1024 * 1024)
#define BQ_H   (16ull * 1024 * 1024)
#define BQ_L   (18ull * 1024 * 1024)
#define BK_H   (20ull * 1024 * 1024)
#define BK_L   (22ull * 1024 * 1024)
#define BV_H   (24ull * 1024 * 1024)
#define BV_L   (26ull * 1024 * 1024)
#define BT_H   (28ull * 1024 * 1024)
#define BT_L   (60ull * 1024 * 1024)

__device__ __nv_bfloat16 g_bfbuf[92ull * 1024ull * 1024ull];

// ---------------------------------------------------------------------------
// PTX helpers
// ---------------------------------------------------------------------------
__device__ __forceinline__ void mma16816(float* c, const uint32_t* a,
                                         const uint32_t* b) {
    asm volatile(
        "mma.sync.aligned.m16n8k16.row.col.f32.bf16.bf16.f32 "
        "{%0,%1,%2,%3}, {%4,%5,%6,%7}, {%8,%9}, {%0,%1,%2,%3};"
        : "+f"(c[0]), "+f"(c[1]), "+f"(c[2]), "+f"(c[3])
        : "r"(a[0]), "r"(a[1]), "r"(a[2]), "r"(a[3]), "r"(b[0]), "r"(b[1]));
}

#define LDSM4(r, addr) \
    asm volatile("ldmatrix.sync.aligned.m8n8.x4.shared.b16 {%0,%1,%2,%3}, [%4];" \
        : "=r"((r)[0]), "=r"((r)[1]), "=r"((r)[2]), "=r"((r)[3]) : "r"(addr))
#define LDSM4T(r, addr) \
    asm volatile("ldmatrix.sync.aligned.m8n8.x4.trans.shared.b16 {%0,%1,%2,%3}, [%4];" \
        : "=r"((r)[0]), "=r"((r)[1]), "=r"((r)[2]), "=r"((r)[3]) : "r"(addr))
#define STS128(addr, r0, r1, r2, r3) \
    asm volatile("st.shared.v4.b32 [%0], {%1,%2,%3,%4};" \
        :: "r"(addr), "r"(r0), "r"(r1), "r"(r2), "r"(r3))

__device__ __forceinline__ void cpa16(uint32_t d, const void* s) {
    asm volatile("cp.async.cg.shared.global [%0], [%1], 16;" :: "r"(d), "l"(s));
}
#define CP_COMMIT() asm volatile("cp.async.commit_group;" ::: "memory")
#define CP_WAIT(n)  asm volatile("cp.async.wait_group %0;" :: "n"(n) : "memory")

#define ASTRIDE 72
#define A_ELEMS (128 * ASTRIDE)
#define B_ELEMS (64  * ASTRIDE)
#define STAGE_ELEMS (A_ELEMS + B_ELEMS)
#define HM_SMEM (2 * STAGE_ELEMS * 2)

// scores smem (bytes): q tiles resident, k double-buffered
#define SCQ_H 0
#define SCQ_L 9216
#define SCK_BASE 18432
#define SCK_KL 18432                  // KL offset within a stage
#define SCK_STAGE 36864               // KH + KL
#define SC_SMEM (SCK_BASE + 2 * SCK_STAGE)   // 92160

// av smem tile offsets (elements within a stage)
#define AV_AFH 0
#define AV_AFL 4608
#define AV_ARH 9216
#define AV_ARL 13824
#define AV_VH  18432
#define AV_VL  23040
#define AV_STAGE 27648
#define AV_SMEM (2 * AV_STAGE * 2)

// ---------------------------------------------------------------------------
__device__ __forceinline__ void split2w(float v0, float v1,
                                        __nv_bfloat16* hp, __nv_bfloat16* lp) {
    __nv_bfloat16 h0 = __float2bfloat16(v0);
    __nv_bfloat16 h1 = __float2bfloat16(v1);
    __nv_bfloat162 hh; hh.x = h0; hh.y = h1;
    __nv_bfloat162 ll;
    ll.x = __float2bfloat16(v0 - __bfloat162float(h0));
    ll.y = __float2bfloat16(v1 - __bfloat162float(h1));
    *(__nv_bfloat162*)hp = hh;
    *(__nv_bfloat162*)lp = ll;
}
__device__ __forceinline__ void split4(const float* v,
                                       __nv_bfloat16* hp, __nv_bfloat16* lp) {
    split2w(v[0], v[1], hp, lp);
    split2w(v[2], v[3], hp + 2, lp + 2);
}

// ---------------------------------------------------------------------------
__global__ __launch_bounds__(NT)
void splitx_kernel(const float* __restrict__ x,
                   __nv_bfloat16* __restrict__ xh,
                   __nv_bfloat16* __restrict__ xl)
{
    const size_t i4 = (size_t)blockIdx.x * NT + threadIdx.x;
    float4 v = ((const float4*)x)[i4];
    float vv[4] = {v.x, v.y, v.z, v.w};
    split4(vv, xh + i4 * 4, xl + i4 * 4);
}

struct WPack { const float* w[7]; };

__global__ __launch_bounds__(NT)
void splitw_kernel(WPack p, __nv_bfloat16* __restrict__ base)
{
    const int wi = blockIdx.z;
    const float* W = p.w[wi];
    __nv_bfloat16* hO = base + (size_t)wi * 524288;
    __nv_bfloat16* lO = hO + 262144;
    __shared__ float t[32][33];
    const int n0 = blockIdx.x * 32, k0 = blockIdx.y * 32;
    const int lane = threadIdx.x & 31, ty = threadIdx.x >> 5;
#pragma unroll
    for (int p2 = 0; p2 < 4; ++p2) {
        int r = p2 * 8 + ty;
        t[r][lane] = W[(size_t)(k0 + r) * 512 + n0 + lane];
    }
    __syncthreads();
#pragma unroll
    for (int p2 = 0; p2 < 4; ++p2) {
        int r = p2 * 8 + ty;
        float v = t[lane][r];
        __nv_bfloat16 h = __float2bfloat16(v);
        __nv_bfloat16 l = __float2bfloat16(v - __bfloat162float(h));
        size_t o = (size_t)(n0 + r) * 512 + k0 + lane;
        hO[o] = h;
        lO[o] = l;
    }
}

// ---------------------------------------------------------------------------
// HMMA GEMM, z-indexed job pack.   (unchanged)
// ---------------------------------------------------------------------------
struct GJob {
    const __nv_bfloat16 *Ah, *Al, *Bh, *Bl;
    const float* bias;
    float* C;
    __nv_bfloat16 *Ch, *Cl;
    int mode;
};
struct GJobs { GJob j[4]; };

__global__ __launch_bounds__(NT)
void hmma_gemm_kernel(GJobs jobs)
{
    const GJob J = jobs.j[blockIdx.z];
    extern __shared__ __align__(16) __nv_bfloat16 smem[];
    const uint32_t smemU = (uint32_t)__cvta_generic_to_shared(smem);
    const int tid = threadIdx.x, lane = tid & 31, wid = tid >> 5;
    const int m0 = blockIdx.y * 128, n0 = blockIdx.x * 64;
    const int wm = (wid & 3) * 32, wn = (wid >> 2) * 32;
    const int arow = tid >> 1, ahof = (tid & 1) * 32;
    const int brow = tid >> 2, bqof = (tid & 3) * 16;

    auto load_chunk = [&](int c, int buf) {
        const int phase = c >> 3, kc = (c & 7) << 6;
        const __nv_bfloat16* As = (phase == 1) ? J.Al : J.Ah;
        const __nv_bfloat16* Bs = (phase == 2) ? J.Bl : J.Bh;
        const uint32_t ab = smemU + buf * (STAGE_ELEMS * 2);
        const uint32_t bb = ab + A_ELEMS * 2;
        const __nv_bfloat16* as = As + (size_t)(m0 + arow) * 512 + kc + ahof;
        const uint32_t ad = ab + (arow * ASTRIDE + ahof) * 2;
#pragma unroll
        for (int i = 0; i < 4; ++i) cpa16(ad + i * 16, as + i * 8);
        const __nv_bfloat16* bs = Bs + (size_t)(n0 + brow) * 512 + kc + bqof;
        const uint32_t bd = bb + (brow * ASTRIDE + bqof) * 2;
#pragma unroll
        for (int i = 0; i < 2; ++i) cpa16(bd + i * 16, bs + i * 8);
        CP_COMMIT();
    };

    float acc[2][4][4] = {};
    const uint32_t aFrag =
        ((wm + (lane & 15)) * ASTRIDE + ((lane >> 4) & 1) * 8) * 2;
    const uint32_t bFrag =
        ((wn + (lane & 7) + ((lane >> 4) & 1) * 8) * ASTRIDE +
         ((lane >> 3) & 1) * 8) * 2;

    auto compute = [&](int buf) {
        const uint32_t ab = smemU + buf * (STAGE_ELEMS * 2);
        const uint32_t aA = ab + aFrag;
        const uint32_t bA = ab + A_ELEMS * 2 + bFrag;
        uint32_t fr[2][16];
        auto ldf = [&](int k16, uint32_t* f) {
            const uint32_t ko = k16 * 32;
            LDSM4(f, aA + ko);
            LDSM4(f + 4, aA + 16 * ASTRIDE * 2 + ko);
            LDSM4(f + 8, bA + ko);
            LDSM4(f + 12, bA + 16 * ASTRIDE * 2 + ko);
        };
        ldf(0, fr[0]);
#pragma unroll
        for (int k16 = 0; k16 < 4; ++k16) {
            if (k16 < 3) ldf(k16 + 1, fr[(k16 + 1) & 1]);
            uint32_t* f = fr[k16 & 1];
            mma16816(acc[0][0], f, f + 8);      mma16816(acc[0][1], f, f + 10);
            mma16816(acc[0][2], f, f + 12);     mma16816(acc[0][3], f, f + 14);
            mma16816(acc[1][0], f + 4, f + 8);  mma16816(acc[1][1], f + 4, f + 10);
            mma16816(acc[1][2], f + 4, f + 12); mma16816(acc[1][3], f + 4, f + 14);
        }
    };

    load_chunk(0, 0);
    for (int c = 0; c < 24; ++c) {
        if (c + 1 < 24) {
            load_chunk(c + 1, (c + 1) & 1);
            CP_WAIT(1);
        } else {
            CP_WAIT(0);
        }
        __syncthreads();
        compute(c & 1);
        __syncthreads();
    }

    const int g = lane >> 2, tg = (lane & 3) * 2;
#pragma unroll
    for (int mi = 0; mi < 2; ++mi) {
        const int r0 = m0 + wm + mi * 16 + g;
#pragma unroll
        for (int ni = 0; ni < 4; ++ni) {
            const int col = n0 + wn + ni * 8 + tg;
            const float b0v = J.bias[col], b1v = J.bias[col + 1];
            float v00 = acc[mi][ni][0] + b0v, v01 = acc[mi][ni][1] + b1v;
            float v10 = acc[mi][ni][2] + b0v, v11 = acc[mi][ni][3] + b1v;
            const size_t o0 = (size_t)r0 * 512 + col;
            const size_t o1 = (size_t)(r0 + 8) * 512 + col;
            if (J.mode == 0) {
                float2 lo = {v00, v01};
                float2 hi = {v10, v11};
                *(float2*)&J.C[o0] = lo;
                *(float2*)&J.C[o1] = hi;
            } else {
                split2w(v00, v01, J.Ch + o0, J.Cl + o0);
                split2w(v10, v11, J.Ch + o1, J.Cl + o1);
            }
        }
    }
}

// ---------------------------------------------------------------------------
// scores v4 (HMMA): per (b,h,q64): At = 0.125 * (qh+ql)(kh+kl)^T  -> fp16
// Frag-shared inner loop: per k16 load qh,ql (2 LDSM4) + kh,kl (8 LDSM4),
// issue all 24 MMAs.  q resident, k streamed double-buffered.
// ---------------------------------------------------------------------------
__global__ __launch_bounds__(NT, 2)
void scores_hmma_kernel(const __nv_bfloat16* __restrict__ qh,
                        const __nv_bfloat16* __restrict__ ql,
                        const __nv_bfloat16* __restrict__ kh,
                        const __nv_bfloat16* __restrict__ kl,
                        __half* __restrict__ At)
{
    extern __shared__ __align__(16) __nv_bfloat16 smem[];
    const uint32_t smemU = (uint32_t)__cvta_generic_to_shared(smem);
    const int bh = blockIdx.y, b = bh >> 3, h = bh & 7;
    const int q0 = blockIdx.x * 64;
    const int tid = threadIdx.x, lane = tid & 31, wid = tid >> 5;
    const int wm = (wid & 3) * 16, wn = (wid >> 2) * 64;

    // q loader: 64 rows x 64 cols, hi+lo
    const int qrow = tid >> 2, qseg = (tid & 3) * 16;
    const size_t qsrc = (size_t)(b * 1024 + q0 + qrow) * 512 + h * 64 + qseg;
    const uint32_t qdst = (qrow * ASTRIDE + qseg) * 2;
    cpa16(smemU + SCQ_H + qdst, qh + qsrc);
    cpa16(smemU + SCQ_H + qdst + 16, qh + qsrc + 8);
    cpa16(smemU + SCQ_L + qdst, ql + qsrc);
    cpa16(smemU + SCQ_L + qdst + 16, ql + qsrc + 8);

    // k loader: 128 rows x 64 cols per chunk, hi+lo
    const int krow = tid >> 1, kseg = (tid & 1) * 32;
    const uint32_t kdstOff = (krow * ASTRIDE + kseg) * 2;

    auto issueK = [&](int c, int buf) {
        const size_t ksrc = (size_t)(b * 1024 + c * 128 + krow) * 512 + h * 64 + kseg;
        const uint32_t kb = smemU + SCK_BASE + buf * SCK_STAGE + kdstOff;
#pragma unroll
        for (int i = 0; i < 4; ++i) cpa16(kb + i * 16, kh + ksrc + i * 8);
#pragma unroll
        for (int i = 0; i < 4; ++i) cpa16(kb + SCK_KL + i * 16, kl + ksrc + i * 8);
        CP_COMMIT();
    };

    const uint32_t aFragOff =
        ((wm + (lane & 15)) * ASTRIDE + ((lane >> 4) & 1) * 8) * 2;
    const uint32_t bFragOff =
        ((wn + (lane & 7) + ((lane >> 4) & 1) * 8) * ASTRIDE +
         ((lane >> 3) & 1) * 8) * 2;

    __half* Cp = At + ((size_t)bh << 20);
    const int g = lane >> 2, tg = (lane & 3) * 2;

    issueK(0, 0);

    for (int c = 0; c < 8; ++c) {
        if (c + 1 < 8) {
            issueK(c + 1, (c + 1) & 1);
            CP_WAIT(1);
        } else {
            CP_WAIT(0);
        }
        __syncthreads();

        float acc[8][4] = {};
        const uint32_t kbase = smemU + SCK_BASE + (c & 1) * SCK_STAGE;
        const uint32_t aH = smemU + SCQ_H + aFragOff;
        const uint32_t aL = smemU + SCQ_L + aFragOff;
        const uint32_t bH = kbase + bFragOff;
        const uint32_t bL = kbase + SCK_KL + bFragOff;
#pragma unroll
        for (int k16 = 0; k16 < 4; ++k16) {
            const uint32_t ko = k16 * 32;
            uint32_t ah4[4], al4[4];
            LDSM4(ah4, aH + ko);
            LDSM4(al4, aL + ko);
            uint32_t bh4[4][4], bl4[4][4];
#pragma unroll
            for (int nj = 0; nj < 4; ++nj) {
                LDSM4(bh4[nj], bH + nj * 16 * ASTRIDE * 2 + ko);
                LDSM4(bl4[nj], bL + nj * 16 * ASTRIDE * 2 + ko);
            }
#pragma unroll
            for (int nj = 0; nj < 4; ++nj) {
                // hh
                mma16816(acc[2 * nj],     ah4, bh4[nj]);
                mma16816(acc[2 * nj + 1], ah4, bh4[nj] + 2);
                // lh
                mma16816(acc[2 * nj],     al4, bh4[nj]);
                mma16816(acc[2 * nj + 1], al4, bh4[nj] + 2);
                // hl
                mma16816(acc[2 * nj],     ah4, bl4[nj]);
                mma16816(acc[2 * nj + 1], ah4, bl4[nj] + 2);
            }
        }

        // write 64 x 128 fp16 tile for this chunk
        const int r0 = q0 + wm + g;
#pragma unroll
        for (int ni = 0; ni < 8; ++ni) {
            const int col = c * 128 + wn + ni * 8 + tg;
            __half2 lo = __floats2half2_rn(acc[ni][0] * 0.125f, acc[ni][1] * 0.125f);
            __half2 hi = __floats2half2_rn(acc[ni][2] * 0.125f, acc[ni][3] * 0.125f);
            *(__half2*)&Cp[(size_t)r0 * 1024 + col] = lo;
            *(__half2*)&Cp[(size_t)(r0 + 8) * 1024 + col] = hi;
        }
        __syncthreads();
    }
}

// ---------------------------------------------------------------------------
// fused softmax / z / masks / stats; reads fp16 At; emits (t-1) bf16 hi/lo
// ---------------------------------------------------------------------------
__device__ __forceinline__ float warpMaxF(float v) {
#pragma unroll
    for (int o = 16; o; o >>= 1) v = fmaxf(v, __shfl_xor_sync(0xffffffffu, v, o));
    return v;
}
__device__ __forceinline__ float warpSumF(float v) {
#pragma unroll
    for (int o = 16; o; o >>= 1) v += __shfl_xor_sync(0xffffffffu, v, o);
    return v;
}

__global__ __launch_bounds__(NT)
void fused_sm_kernel(const __half* __restrict__ At,
                     const float* __restrict__ cw,
                     const float* __restrict__ cbp,
                     unsigned char* __restrict__ maskbuf,
                     float* __restrict__ stats,
                     __nv_bfloat16* __restrict__ tdh,
                     __nv_bfloat16* __restrict__ tdl)
{
    const int bq = blockIdx.x;
    const int b  = bq >> 10;
    const int q  = bq & 1023;
    const int tid  = threadIdx.x;
    const int lane = tid & 31, wid = tid >> 5;

    __shared__ float red[16][8];
    __shared__ float fin[16];

    const float cb = cbp[0];
    const size_t rowbase = ((size_t)q << 10) + (size_t)tid * 4;

    float a[8][4];
    float lm[8];
#pragma unroll
    for (int h = 0; h < 8; ++h) {
        uint2 u = *(const uint2*)(At + (size_t)(b * 8 + h) * 1048576 + rowbase);
        float2 f0 = __half22float2(*(__half2*)&u.x);
        float2 f1 = __half22float2(*(__half2*)&u.y);
        a[h][0] = f0.x; a[h][1] = f0.y; a[h][2] = f1.x; a[h][3] = f1.y;
        lm[h] = fmaxf(fmaxf(a[h][0], a[h][1]), fmaxf(a[h][2], a[h][3]));
    }
#pragma unroll
    for (int h = 0; h < 8; ++h) {
        float w = warpMaxF(lm[h]);
        if (lane == 0) red[h][wid] = w;
    }
    __syncthreads();
    if (tid < 8) {
        float m = red[tid][0];
#pragma unroll
        for (int i = 1; i < 8; ++i) m = fmaxf(m, red[tid][i]);
        fin[tid] = m;
    }
    __syncthreads();
    float ls[8];
#pragma unroll
    for (int h = 0; h < 8; ++h) {
        float m = fin[h];
        float s = 0.f;
#pragma unroll
        for (int j = 0; j < 4; ++j) {
            a[h][j] = __expf(a[h][j] - m);
            s += a[h][j];
        }
        ls[h] = s;
    }
    __syncthreads();
#pragma unroll
    for (int h = 0; h < 8; ++h) {
        float w = warpSumF(ls[h]);
        if (lane == 0) red[h][wid] = w;
    }
    __syncthreads();
    if (tid < 8) {
        float s = red[tid][0];
#pragma unroll
        for (int i = 1; i < 8; ++i) s += red[tid][i];
        fin[tid] = 1.0f / s;
    }
    __syncthreads();

    float zacc[4] = {cb, cb, cb, cb};
#pragma unroll
    for (int h = 0; h < 8; ++h) {
        float inv = fin[h];
        float w   = cw[h];
#pragma unroll
        for (int j = 0; j < 4; ++j) {
            a[h][j] *= inv;
            zacc[j] = fmaf(a[h][j], w, zacc[j]);
        }
    }
    unsigned mby[4];
#pragma unroll
    for (int j = 0; j < 4; ++j) {
        unsigned mf = (zacc[j] <= 0.f) ? 1u : 0u;
        unsigned mr = (zacc[j] >= 0.f) ? 2u : 0u;
        mby[j] = mf | mr;
    }

    float lsf[8], lsr[8];
#pragma unroll
    for (int h = 0; h < 8; ++h) {
        float sf = 0.f, sr = 0.f;
#pragma unroll
        for (int j = 0; j < 4; ++j) {
            float t = __expf(a[h][j]);
            a[h][j] = t;
            sf += (mby[j] & 1u) ? t : 1.0f;
            sr += (mby[j] & 2u) ? t : 1.0f;
        }
        lsf[h] = sf; lsr[h] = sr;
    }
    __syncthreads();
#pragma unroll
    for (int h = 0; h < 8; ++h) {
        float w = warpSumF(lsf[h]);
        if (lane == 0) red[h][wid] = w;
        w = warpSumF(lsr[h]);
        if (lane == 0) red[8 + h][wid] = w;
    }
    __syncthreads();
    if (tid < 16) {
        float s = red[tid][0];
#pragma unroll
        for (int i = 1; i < 8; ++i) s += red[tid][i];
        float inv = 1.0f / s;
        int h = tid & 7;
        int row = (b * 8 + h) * 1024 + q;
        if (tid < 8) stats[row] = inv;
        else         stats[32768 + row] = inv;
    }

#pragma unroll
    for (int h = 0; h < 8; ++h) {
        size_t o = (size_t)(b * 8 + h) * 1048576 + rowbase;
        split2w(a[h][0] - 1.0f, a[h][1] - 1.0f, tdh + o, tdl + o);
        split2w(a[h][2] - 1.0f, a[h][3] - 1.0f, tdh + o + 2, tdl + o + 2);
    }
    uchar4 m4 = {(unsigned char)mby[0], (unsigned char)mby[1],
                 (unsigned char)mby[2], (unsigned char)mby[3]};
    *(uchar4*)(maskbuf + (size_t)bq * 1024 + tid * 4) = m4;
}

// ---------------------------------------------------------------------------
// colsum[bh][d] = sum_k (vh+vl)[b,k,h*64+d]
// ---------------------------------------------------------------------------
__global__ __launch_bounds__(NT)
void colsum_kernel(const __nv_bfloat16* __restrict__ vh,
                   const __nv_bfloat16* __restrict__ vl,
                   float* __restrict__ cs)
{
    const int bh = blockIdx.x, b = bh >> 3, h = bh & 7;
    const int tid = threadIdx.x;
    const int d = tid & 63, part = tid >> 6;
    __shared__ float red[4][64];
    const __nv_bfloat16* p1 = vh + ((size_t)(b * 1024 + part * 256)) * 512 + h * 64 + d;
    const __nv_bfloat16* p2 = vl + ((size_t)(b * 1024 + part * 256)) * 512 + h * 64 + d;
    float s = 0.f;
    for (int k = 0; k < 256; ++k)
        s += __bfloat162float(p1[(size_t)k * 512]) + __bfloat162float(p2[(size_t)k * 512]);
    red[part][d] = s;
    __syncthreads();
    if (tid < 64)
        cs[bh * 64 + tid] = red[0][tid] + red[1][tid] + red[2][tid] + red[3][tid];
}

// ---------------------------------------------------------------------------
// av (HMMA): per (b,h), q-tile 64  (unchanged round-13 config)
// ---------------------------------------------------------------------------
__global__ __launch_bounds__(NT)
void av_hmma_kernel(const __nv_bfloat16* __restrict__ tdh,
                    const __nv_bfloat16* __restrict__ tdl,
                    const unsigned char* __restrict__ maskb,
                    const float* __restrict__ stats,
                    const float* __restrict__ colsum,
                    const __nv_bfloat16* __restrict__ vh,
                    const __nv_bfloat16* __restrict__ vl,
                    __nv_bfloat16* __restrict__ Tfh, __nv_bfloat16* __restrict__ Tfl,
                    __nv_bfloat16* __restrict__ Trh, __nv_bfloat16* __restrict__ Trl)
{
    extern __shared__ __align__(16) __nv_bfloat16 smem[];
    const uint32_t smemU = (uint32_t)__cvta_generic_to_shared(smem);
    const int bh = blockIdx.y, b = bh >> 3, h = bh & 7;
    const int q0 = blockIdx.x * 64;
    const int tid = threadIdx.x, lane = tid & 31, wid = tid >> 5;
    const int branch = wid >> 2;
    const int wq = (wid & 3) * 16;

    const int row = tid >> 2, seg = (tid & 3) * 16;

    const __nv_bfloat16* thp = tdh + (size_t)bh * 1048576 + (size_t)(q0 + row) * 1024 + seg;
    const __nv_bfloat16* tlp = tdl + (size_t)bh * 1048576 + (size_t)(q0 + row) * 1024 + seg;
    const unsigned char* mp  = maskb + ((size_t)(b * 1024 + q0 + row)) * 1024 + seg;
    const __nv_bfloat16* vhp = vh + ((size_t)(b * 1024 + row)) * 512 + h * 64 + seg;
    const __nv_bfloat16* vlp = vl + ((size_t)(b * 1024 + row)) * 512 + h * 64 + seg;

    uint4 thR[2], tlR[2], mkR;
    auto loadA = [&](int c) {
        const int k0 = c * 64;
        thR[0] = *(const uint4*)(thp + k0);
        thR[1] = *(const uint4*)(thp + k0 + 8);
        tlR[0] = *(const uint4*)(tlp + k0);
        tlR[1] = *(const uint4*)(tlp + k0 + 8);
        mkR    = *(const uint4*)(mp + k0);
    };
    auto issueV = [&](int c, int buf) {
        const size_t ko = (size_t)c * 64 * 512;
        const uint32_t base = smemU + buf * (AV_STAGE * 2) + (row * ASTRIDE + seg) * 2;
        cpa16(base + AV_VH * 2,      vhp + ko);
        cpa16(base + AV_VH * 2 + 16, vhp + ko + 8);
        cpa16(base + AV_VL * 2,      vlp + ko);
        cpa16(base + AV_VL * 2 + 16, vlp + ko + 8);
        CP_COMMIT();
    };
    auto selstore = [&](int buf) {
        const uint32_t* thw = (const uint32_t*)thR;
        const uint32_t* tlw = (const uint32_t*)tlR;
        uint32_t mkw[4] = {mkR.x, mkR.y, mkR.z, mkR.w};
        uint32_t afh[8], afl[8], arh[8], arl[8];
#pragma unroll
        for (int i = 0; i < 8; ++i) {
            uint32_t mw = mkw[i >> 1];
            uint32_t sh = (i & 1) * 16;
            uint32_t m0 = (mw >> sh) & 0xFFu;
            uint32_t m1 = (mw >> (sh + 8)) & 0xFFu;
            uint32_t sF = ((m0 & 1u) ? 0x0000FFFFu : 0u) | ((m1 & 1u) ? 0xFFFF0000u : 0u);
            uint32_t sR = ((m0 & 2u) ? 0x0000FFFFu : 0u) | ((m1 & 2u) ? 0xFFFF0000u : 0u);
            afh[i] = thw[i] & sF;  arh[i] = thw[i] & sR;
            afl[i] = tlw[i] & sF;  arl[i] = tlw[i] & sR;
        }
        const uint32_t base = smemU + buf * (AV_STAGE * 2) + (row * ASTRIDE + seg) * 2;
        STS128(base + AV_AFH * 2,      afh[0], afh[1], afh[2], afh[3]);
        STS128(base + AV_AFH * 2 + 16, afh[4], afh[5], afh[6], afh[7]);
        STS128(base + AV_AFL * 2,      afl[0], afl[1], afl[2], afl[3]);
        STS128(base + AV_AFL * 2 + 16, afl[4], afl[5], afl[6], afl[7]);
        STS128(base + AV_ARH * 2,      arh[0], arh[1], arh[2], arh[3]);
        STS128(base + AV_ARH * 2 + 16, arh[4], arh[5], arh[6], arh[7]);
        STS128(base + AV_ARL * 2,      arl[0], arl[1], arl[2], arl[3]);
        STS128(base + AV_ARL * 2 + 16, arl[4], arl[5], arl[6], arl[7]);
    };

    float acc[8][4] = {};
    const uint32_t aOffH = (branch ? AV_ARH : AV_AFH) * 2 +
        ((wq + (lane & 15)) * ASTRIDE + ((lane >> 4) & 1) * 8) * 2;
    const uint32_t aOffL = (branch ? AV_ARL : AV_AFL) * 2 +
        ((wq + (lane & 15)) * ASTRIDE + ((lane >> 4) & 1) * 8) * 2;
    const uint32_t vLaneOff = ((lane & 15) * ASTRIDE + ((lane >> 4) & 1) * 8) * 2;

    auto compute = [&](int buf) {
        const uint32_t sb = smemU + buf * (AV_STAGE * 2);
#pragma unroll
        for (int k16 = 0; k16 < 4; ++k16) {
            uint32_t ah[4], al[4], fvh[16], fvl[16];
            LDSM4(ah, sb + aOffH + k16 * 32);
            LDSM4(al, sb + aOffL + k16 * 32);
            const uint32_t vkb = sb + vLaneOff + k16 * 16 * ASTRIDE * 2;
#pragma unroll
            for (int g = 0; g < 4; ++g) {
                LDSM4T(fvh + 4 * g, vkb + AV_VH * 2 + g * 32);
                LDSM4T(fvl + 4 * g, vkb + AV_VL * 2 + g * 32);
            }
#pragma unroll
            for (int n = 0; n < 8; ++n) {
                uint32_t* bh2 = fvh + 4 * (n >> 1) + 2 * (n & 1);
                uint32_t* bl2 = fvl + 4 * (n >> 1) + 2 * (n & 1);
                mma16816(acc[n], ah, bh2);
                mma16816(acc[n], ah, bl2);
                mma16816(acc[n], al, bh2);
            }
        }
    };

    loadA(0);
    issueV(0, 0);
    selstore(0);
    CP_WAIT(0);
    __syncthreads();

    for (int c = 0; c < 16; ++c) {
        const int cur = c & 1;
        const bool more = (c + 1) < 16;
        if (more) { issueV(c + 1, cur ^ 1); loadA(c + 1); }
        compute(cur);
        __syncthreads();
        if (more) {
            selstore(cur ^ 1);
            CP_WAIT(0);
            __syncthreads();
        }
    }

    const int g = lane >> 2, tg = (lane & 3) * 2;
    const int q1 = q0 + wq + g, q2 = q1 + 8;
    const int srow = (branch ? 32768 : 0) + bh * 1024;
    const float rs1 = stats[srow + q1];
    const float rs2 = stats[srow + q2];
    __nv_bfloat16* outH = branch ? Trh : Tfh;
    __nv_bfloat16* outL = branch ? Trl : Tfl;
#pragma unroll
    for (int n = 0; n < 8; ++n) {
        const int d = n * 8 + tg;
        const float cs0 = colsum[bh * 64 + d];
        const float cs1 = colsum[bh * 64 + d + 1];
        const size_t o1 = (size_t)(b * 1024 + q1) * 512 + h * 64 + d;
        const size_t o2 = (size_t)(b * 1024 + q2) * 512 + h * 64 + d;
        split2w((acc[n][0] + cs0) * rs1, (acc[n][1] + cs1) * rs1, outH + o1, outL + o1);
        split2w((acc[n][2] + cs0) * rs2, (acc[n][3] + cs1) * rs2, outH + o2, outL + o2);
    }
}

// ---------------------------------------------------------------------------
__global__ __launch_bounds__(NT)
void combine_kernel(const float* __restrict__ Ff, const float* __restrict__ Gf,
                    const float* __restrict__ Fr, const float* __restrict__ Gr,
                    float* __restrict__ out)
{
    const size_t i4 = (size_t)blockIdx.x * NT + threadIdx.x;
    float4 ff = ((const float4*)Ff)[i4];
    float4 gf = ((const float4*)Gf)[i4];
    float4 fr = ((const float4*)Fr)[i4];
    float4 gr = ((const float4*)Gr)[i4];

    float ffv[4] = {ff.x, ff.y, ff.z, ff.w};
    float gfv[4] = {gf.x, gf.y, gf.z, gf.w};
    float frv[4] = {fr.x, fr.y, fr.z, fr.w};
    float grv[4] = {gr.x, gr.y, gr.z, gr.w};
    float ov[4];
#pragma unroll
    for (int j = 0; j < 4; ++j) {
        float sgf = 1.0f / (1.0f + __expf(-gfv[j]));
        float sgr = 1.0f / (1.0f + __expf(-grv[j]));
        float w   = 1.0f / (1.0f + __expf(sgr - sgf));
        ov[j] = ffv[j] * w + frv[j] * (1.0f - w);
    }
    float4 o = {ov[0], ov[1], ov[2], ov[3]};
    ((float4*)out)[i4] = o;
}

// ---------------------------------------------------------------------------
extern "C" void kernel_launch(void* const* d_in, const int* in_sizes, int n_in,
                              void* d_out, int out_size)
{
    const float* x   = (const float*)d_in[0];
    const float* Wq  = (const float*)d_in[1];
    const float* bq  = (const float*)d_in[2];
    const float* Wk  = (const float*)d_in[3];
    const float* bk  = (const float*)d_in[4];
    const float* Wv  = (const float*)d_in[5];
    const float* bv  = (const float*)d_in[6];
    const float* cw  = (const float*)d_in[7];
    const float* cb  = (const float*)d_in[8];
    const float* Wfh = (const float*)d_in[9];
    const float* bfh = (const float*)d_in[10];
    const float* Wfg = (const float*)d_in[11];
    const float* bfg = (const float*)d_in[12];
    const float* Wrh = (const float*)d_in[13];
    const float* brh = (const float*)d_in[14];
    const float* Wrg = (const float*)d_in[15];
    const float* brg = (const float*)d_in[16];
    float* out = (float*)d_out;

    float* s = nullptr;
    cudaGetSymbolAddress((void**)&s, g_scratch);
    __nv_bfloat16* bb = nullptr;
    cudaGetSymbolAddress((void**)&bb, g_bfbuf);

    float* Ff    = s + OFF_FF;
    float* Gf    = s + OFF_GF;
    float* Fr    = s + OFF_FR;
    float* Gr    = s + OFF_GR;
    unsigned char* maskb = (unsigned char*)(s + OFF_MB);
    float* stats = s + OFF_ST;
    float* csum  = s + OFF_CS;
    __half* At   = (__half*)(s + OFF_AT);

    __nv_bfloat16* xh  = bb + BX_H;
    __nv_bfloat16* xl  = bb + BX_L;
    __nv_bfloat16* tfh = bb + BTF_H;
    __nv_bfloat16* tfl = bb + BTF_L;
    __nv_bfloat16* trh = bb + BTR_H;
    __nv_bfloat16* trl = bb + BTR_L;
    __nv_bfloat16* wb  = bb + BW;
    __nv_bfloat16* qhb = bb + BQ_H;
    __nv_bfloat16* qlb = bb + BQ_L;
    __nv_bfloat16* khb = bb + BK_H;
    __nv_bfloat16* klb = bb + BK_L;
    __nv_bfloat16* vhb = bb + BV_H;
    __nv_bfloat16* vlb = bb + BV_L;
    __nv_bfloat16* tdh = bb + BT_H;
    __nv_bfloat16* tdl = bb + BT_L;

    cudaFuncSetAttribute(hmma_gemm_kernel,
                         cudaFuncAttributeMaxDynamicSharedMemorySize, HM_SMEM);
    cudaFuncSetAttribute(scores_hmma_kernel,
                         cudaFuncAttributeMaxDynamicSharedMemorySize, SC_SMEM);
    cudaFuncSetAttribute(av_hmma_kernel,
                         cudaFuncAttributeMaxDynamicSharedMemorySize, AV_SMEM);

    WPack wp;
    wp.w[0] = Wq;  wp.w[1] = Wk;  wp.w[2] = Wv;
    wp.w[3] = Wfh; wp.w[4] = Wfg; wp.w[5] = Wrh; wp.w[6] = Wrg;
    splitw_kernel<<<dim3(16, 16, 7), NT>>>(wp, wb);
    splitx_kernel<<<2048, NT>>>(x, xh, xl);

    GJobs qkv = {};
    qkv.j[0] = {xh, xl, wb + 0 * 524288, wb + 0 * 524288 + 262144, bq, nullptr, qhb, qlb, 1};
    qkv.j[1] = {xh, xl, wb + 1 * 524288, wb + 1 * 524288 + 262144, bk, nullptr, khb, klb, 1};
    qkv.j[2] = {xh, xl, wb + 2 * 524288, wb + 2 * 524288 + 262144, bv, nullptr, vhb, vlb, 1};
    hmma_gemm_kernel<<<dim3(8, 32, 3), NT, HM_SMEM>>>(qkv);

    scores_hmma_kernel<<<dim3(16, 32), NT, SC_SMEM>>>(qhb, qlb, khb, klb, At);
    fused_sm_kernel<<<4096, NT>>>(At, cw, cb, maskb, stats, tdh, tdl);
    colsum_kernel<<<32, NT>>>(vhb, vlb, csum);
    av_hmma_kernel<<<dim3(16, 32), NT, AV_SMEM>>>(tdh, tdl, maskb, stats, csum,
                                                  vhb, vlb, tfh, tfl, trh, trl);

    GJobs fin = {};
    fin.j[0] = {tfh, tfl, wb + 3 * 524288, wb + 3 * 524288 + 262144, bfh, Ff, nullptr, nullptr, 0};
    fin.j[1] = {tfh, tfl, wb + 4 * 524288, wb + 4 * 524288 + 262144, bfg, Gf, nullptr, nullptr, 0};
    fin.j[2] = {trh, trl, wb + 5 * 524288, wb + 5 * 524288 + 262144, brh, Fr, nullptr, nullptr, 0};
    fin.j[3] = {trh, trl, wb + 6 * 524288, wb + 6 * 524288 + 262144, brg, Gr, nullptr, nullptr, 0};
    hmma_gemm_kernel<<<dim3(8, 32, 4), NT, HM_SMEM>>>(fin);

    combine_kernel<<<2048, NT>>>(Ff, Gf, Fr, Gr, out);
}

// round 17
// speedup vs baseline: 1.0655x; 1.0009x over previous
#include <cuda_runtime.h>
#include <cuda_bf16.h>
#include <cuda_fp16.h>
#include <cstdint>

// ---------------------------------------------------------------------------
// ComplementaryAttention  B=4 T=1024 D=512 H=8 hd=64   (round 17)
//   - scores v5: 2q x 4k warp layout (8 LDSM / 24 MMA) + fragment
//     double-buffering across k16
//   - av: pipelined v-fragment loads (2 LDSM4T hidden behind 6 MMAs)
// ---------------------------------------------------------------------------

#define NT 256

// fp32 scratch (floats)
#define OFF_FF  (10ull * 1024 * 1024)
#define OFF_GF  (12ull * 1024 * 1024)
#define OFF_FR  (14ull * 1024 * 1024)
#define OFF_GR  (16ull * 1024 * 1024)
#define OFF_MB  (18ull * 1024 * 1024)
#define OFF_ST  (22ull * 1024 * 1024)
#define OFF_CS  (22ull * 1024 * 1024 + 131072)
#define OFF_AT  (23ull * 1024 * 1024)   // __half buffer (32M halves)

__device__ float g_scratch[56ull * 1024ull * 1024ull];

// bf16 scratch (elements)
#define BX_H   (0ull)
#define BX_L   (2ull  * 1024 * 1024)
#define BTF_H  (4ull  * 1024 * 1024)
#define BTF_L  (6ull  * 1024 * 1024)
#define BTR_H  (8ull  * 1024 * 1024)
#define BTR_L  (10ull * 1024 * 1024)
#define BW     (12ull * 1024 * 1024)
#define BQ_H   (16ull * 1024 * 1024)
#define BQ_L   (18ull * 1024 * 1024)
#define BK_H   (20ull * 1024 * 1024)
#define BK_L   (22ull * 1024 * 1024)
#define BV_H   (24ull * 1024 * 1024)
#define BV_L   (26ull * 1024 * 1024)
#define BT_H   (28ull * 1024 * 1024)
#define BT_L   (60ull * 1024 * 1024)

__device__ __nv_bfloat16 g_bfbuf[92ull * 1024ull * 1024ull];

// ---------------------------------------------------------------------------
// PTX helpers
// ---------------------------------------------------------------------------
__device__ __forceinline__ void mma16816(float* c, const uint32_t* a,
                                         const uint32_t* b) {
    asm volatile(
        "mma.sync.aligned.m16n8k16.row.col.f32.bf16.bf16.f32 "
        "{%0,%1,%2,%3}, {%4,%5,%6,%7}, {%8,%9}, {%0,%1,%2,%3};"
        : "+f"(c[0]), "+f"(c[1]), "+f"(c[2]), "+f"(c[3])
        : "r"(a[0]), "r"(a[1]), "r"(a[2]), "r"(a[3]), "r"(b[0]), "r"(b[1]));
}

#define LDSM4(r, addr) \
    asm volatile("ldmatrix.sync.aligned.m8n8.x4.shared.b16 {%0,%1,%2,%3}, [%4];" \
        : "=r"((r)[0]), "=r"((r)[1]), "=r"((r)[2]), "=r"((r)[3]) : "r"(addr))
#define LDSM4T(r, addr) \
    asm volatile("ldmatrix.sync.aligned.m8n8.x4.trans.shared.b16 {%0,%1,%2,%3}, [%4];" \
        : "=r"((r)[0]), "=r"((r)[1]), "=r"((r)[2]), "=r"((r)[3]) : "r"(addr))
#define STS128(addr, r0, r1, r2, r3) \
    asm volatile("st.shared.v4.b32 [%0], {%1,%2,%3,%4};" \
        :: "r"(addr), "r"(r0), "r"(r1), "r"(r2), "r"(r3))

__device__ __forceinline__ void cpa16(uint32_t d, const void* s) {
    asm volatile("cp.async.cg.shared.global [%0], [%1], 16;" :: "r"(d), "l"(s));
}
#define CP_COMMIT() asm volatile("cp.async.commit_group;" ::: "memory")
#define CP_WAIT(n)  asm volatile("cp.async.wait_group %0;" :: "n"(n) : "memory")

#define ASTRIDE 72
#define A_ELEMS (128 * ASTRIDE)
#define B_ELEMS (64  * ASTRIDE)
#define STAGE_ELEMS (A_ELEMS + B_ELEMS)
#define HM_SMEM (2 * STAGE_ELEMS * 2)

// scores smem (bytes): q tiles resident, k double-buffered
#define SCQ_H 0
#define SCQ_L 9216
#define SCK_BASE 18432
#define SCK_KL 18432                  // KL offset within a stage
#define SCK_STAGE 36864               // KH + KL
#define SC_SMEM (SCK_BASE + 2 * SCK_STAGE)   // 92160

// av smem tile offsets (elements within a stage)
#define AV_AFH 0
#define AV_AFL 4608
#define AV_ARH 9216
#define AV_ARL 13824
#define AV_VH  18432
#define AV_VL  23040
#define AV_STAGE 27648
#define AV_SMEM (2 * AV_STAGE * 2)

// ---------------------------------------------------------------------------
__device__ __forceinline__ void split2w(float v0, float v1,
                                        __nv_bfloat16* hp, __nv_bfloat16* lp) {
    __nv_bfloat16 h0 = __float2bfloat16(v0);
    __nv_bfloat16 h1 = __float2bfloat16(v1);
    __nv_bfloat162 hh; hh.x = h0; hh.y = h1;
    __nv_bfloat162 ll;
    ll.x = __float2bfloat16(v0 - __bfloat162float(h0));
    ll.y = __float2bfloat16(v1 - __bfloat162float(h1));
    *(__nv_bfloat162*)hp = hh;
    *(__nv_bfloat162*)lp = ll;
}
__device__ __forceinline__ void split4(const float* v,
                                       __nv_bfloat16* hp, __nv_bfloat16* lp) {
    split2w(v[0], v[1], hp, lp);
    split2w(v[2], v[3], hp + 2, lp + 2);
}

// ---------------------------------------------------------------------------
__global__ __launch_bounds__(NT)
void splitx_kernel(const float* __restrict__ x,
                   __nv_bfloat16* __restrict__ xh,
                   __nv_bfloat16* __restrict__ xl)
{
    const size_t i4 = (size_t)blockIdx.x * NT + threadIdx.x;
    float4 v = ((const float4*)x)[i4];
    float vv[4] = {v.x, v.y, v.z, v.w};
    split4(vv, xh + i4 * 4, xl + i4 * 4);
}

struct WPack { const float* w[7]; };

__global__ __launch_bounds__(NT)
void splitw_kernel(WPack p, __nv_bfloat16* __restrict__ base)
{
    const int wi = blockIdx.z;
    const float* W = p.w[wi];
    __nv_bfloat16* hO = base + (size_t)wi * 524288;
    __nv_bfloat16* lO = hO + 262144;
    __shared__ float t[32][33];
    const int n0 = blockIdx.x * 32, k0 = blockIdx.y * 32;
    const int lane = threadIdx.x & 31, ty = threadIdx.x >> 5;
#pragma unroll
    for (int p2 = 0; p2 < 4; ++p2) {
        int r = p2 * 8 + ty;
        t[r][lane] = W[(size_t)(k0 + r) * 512 + n0 + lane];
    }
    __syncthreads();
#pragma unroll
    for (int p2 = 0; p2 < 4; ++p2) {
        int r = p2 * 8 + ty;
        float v = t[lane][r];
        __nv_bfloat16 h = __float2bfloat16(v);
        __nv_bfloat16 l = __float2bfloat16(v - __bfloat162float(h));
        size_t o = (size_t)(n0 + r) * 512 + k0 + lane;
        hO[o] = h;
        lO[o] = l;
    }
}

// ---------------------------------------------------------------------------
// HMMA GEMM, z-indexed job pack.   (unchanged, validated)
// ---------------------------------------------------------------------------
struct GJob {
    const __nv_bfloat16 *Ah, *Al, *Bh, *Bl;
    const float* bias;
    float* C;
    __nv_bfloat16 *Ch, *Cl;
    int mode;
};
struct GJobs { GJob j[4]; };

__global__ __launch_bounds__(NT)
void hmma_gemm_kernel(GJobs jobs)
{
    const GJob J = jobs.j[blockIdx.z];
    extern __shared__ __align__(16) __nv_bfloat16 smem[];
    const uint32_t smemU = (uint32_t)__cvta_generic_to_shared(smem);
    const int tid = threadIdx.x, lane = tid & 31, wid = tid >> 5;
    const int m0 = blockIdx.y * 128, n0 = blockIdx.x * 64;
    const int wm = (wid & 3) * 32, wn = (wid >> 2) * 32;
    const int arow = tid >> 1, ahof = (tid & 1) * 32;
    const int brow = tid >> 2, bqof = (tid & 3) * 16;

    auto load_chunk = [&](int c, int buf) {
        const int phase = c >> 3, kc = (c & 7) << 6;
        const __nv_bfloat16* As = (phase == 1) ? J.Al : J.Ah;
        const __nv_bfloat16* Bs = (phase == 2) ? J.Bl : J.Bh;
        const uint32_t ab = smemU + buf * (STAGE_ELEMS * 2);
        const uint32_t bb = ab + A_ELEMS * 2;
        const __nv_bfloat16* as = As + (size_t)(m0 + arow) * 512 + kc + ahof;
        const uint32_t ad = ab + (arow * ASTRIDE + ahof) * 2;
#pragma unroll
        for (int i = 0; i < 4; ++i) cpa16(ad + i * 16, as + i * 8);
        const __nv_bfloat16* bs = Bs + (size_t)(n0 + brow) * 512 + kc + bqof;
        const uint32_t bd = bb + (brow * ASTRIDE + bqof) * 2;
#pragma unroll
        for (int i = 0; i < 2; ++i) cpa16(bd + i * 16, bs + i * 8);
        CP_COMMIT();
    };

    float acc[2][4][4] = {};
    const uint32_t aFrag =
        ((wm + (lane & 15)) * ASTRIDE + ((lane >> 4) & 1) * 8) * 2;
    const uint32_t bFrag =
        ((wn + (lane & 7) + ((lane >> 4) & 1) * 8) * ASTRIDE +
         ((lane >> 3) & 1) * 8) * 2;

    auto compute = [&](int buf) {
        const uint32_t ab = smemU + buf * (STAGE_ELEMS * 2);
        const uint32_t aA = ab + aFrag;
        const uint32_t bA = ab + A_ELEMS * 2 + bFrag;
        uint32_t fr[2][16];
        auto ldf = [&](int k16, uint32_t* f) {
            const uint32_t ko = k16 * 32;
            LDSM4(f, aA + ko);
            LDSM4(f + 4, aA + 16 * ASTRIDE * 2 + ko);
            LDSM4(f + 8, bA + ko);
            LDSM4(f + 12, bA + 16 * ASTRIDE * 2 + ko);
        };
        ldf(0, fr[0]);
#pragma unroll
        for (int k16 = 0; k16 < 4; ++k16) {
            if (k16 < 3) ldf(k16 + 1, fr[(k16 + 1) & 1]);
            uint32_t* f = fr[k16 & 1];
            mma16816(acc[0][0], f, f + 8);      mma16816(acc[0][1], f, f + 10);
            mma16816(acc[0][2], f, f + 12);     mma16816(acc[0][3], f, f + 14);
            mma16816(acc[1][0], f + 4, f + 8);  mma16816(acc[1][1], f + 4, f + 10);
            mma16816(acc[1][2], f + 4, f + 12); mma16816(acc[1][3], f + 4, f + 14);
        }
    };

    load_chunk(0, 0);
    for (int c = 0; c < 24; ++c) {
        if (c + 1 < 24) {
            load_chunk(c + 1, (c + 1) & 1);
            CP_WAIT(1);
        } else {
            CP_WAIT(0);
        }
        __syncthreads();
        compute(c & 1);
        __syncthreads();
    }

    const int g = lane >> 2, tg = (lane & 3) * 2;
#pragma unroll
    for (int mi = 0; mi < 2; ++mi) {
        const int r0 = m0 + wm + mi * 16 + g;
#pragma unroll
        for (int ni = 0; ni < 4; ++ni) {
            const int col = n0 + wn + ni * 8 + tg;
            const float b0v = J.bias[col], b1v = J.bias[col + 1];
            float v00 = acc[mi][ni][0] + b0v, v01 = acc[mi][ni][1] + b1v;
            float v10 = acc[mi][ni][2] + b0v, v11 = acc[mi][ni][3] + b1v;
            const size_t o0 = (size_t)r0 * 512 + col;
            const size_t o1 = (size_t)(r0 + 8) * 512 + col;
            if (J.mode == 0) {
                float2 lo = {v00, v01};
                float2 hi = {v10, v11};
                *(float2*)&J.C[o0] = lo;
                *(float2*)&J.C[o1] = hi;
            } else {
                split2w(v00, v01, J.Ch + o0, J.Cl + o0);
                split2w(v10, v11, J.Ch + o1, J.Cl + o1);
            }
        }
    }
}

// ---------------------------------------------------------------------------
// scores v5 (HMMA): per (b,h,q64): At = 0.125 * (qh+ql)(kh+kl)^T -> fp16
// Warp layout 2q x 4k (warp tile 32x32), 8 LDSM / 24 MMA per k16,
// fragment double-buffered across k16.  q resident, k streamed.
// ---------------------------------------------------------------------------
__global__ __launch_bounds__(NT, 2)
void scores_hmma_kernel(const __nv_bfloat16* __restrict__ qh,
                        const __nv_bfloat16* __restrict__ ql,
                        const __nv_bfloat16* __restrict__ kh,
                        const __nv_bfloat16* __restrict__ kl,
                        __half* __restrict__ At)
{
    extern __shared__ __align__(16) __nv_bfloat16 smem[];
    const uint32_t smemU = (uint32_t)__cvta_generic_to_shared(smem);
    const int bh = blockIdx.y, b = bh >> 3, h = bh & 7;
    const int q0 = blockIdx.x * 64;
    const int tid = threadIdx.x, lane = tid & 31, wid = tid >> 5;
    const int wq = (wid & 1) * 32;     // q offset within 64
    const int wk = (wid >> 1) * 32;    // k offset within 128-chunk

    // q loader: 64 rows x 64 cols, hi+lo
    const int qrow = tid >> 2, qseg = (tid & 3) * 16;
    const size_t qsrc = (size_t)(b * 1024 + q0 + qrow) * 512 + h * 64 + qseg;
    const uint32_t qdst = (qrow * ASTRIDE + qseg) * 2;
    cpa16(smemU + SCQ_H + qdst, qh + qsrc);
    cpa16(smemU + SCQ_H + qdst + 16, qh + qsrc + 8);
    cpa16(smemU + SCQ_L + qdst, ql + qsrc);
    cpa16(smemU + SCQ_L + qdst + 16, ql + qsrc + 8);

    // k loader: 128 rows x 64 cols per chunk, hi+lo
    const int krow = tid >> 1, kseg = (tid & 1) * 32;
    const uint32_t kdstOff = (krow * ASTRIDE + kseg) * 2;

    auto issueK = [&](int c, int buf) {
        const size_t ksrc = (size_t)(b * 1024 + c * 128 + krow) * 512 + h * 64 + kseg;
        const uint32_t kb = smemU + SCK_BASE + buf * SCK_STAGE + kdstOff;
#pragma unroll
        for (int i = 0; i < 4; ++i) cpa16(kb + i * 16, kh + ksrc + i * 8);
#pragma unroll
        for (int i = 0; i < 4; ++i) cpa16(kb + SCK_KL + i * 16, kl + ksrc + i * 8);
        CP_COMMIT();
    };

    // fragment addresses
    const uint32_t aFragOff =
        ((wq + (lane & 15)) * ASTRIDE + ((lane >> 4) & 1) * 8) * 2;
    const uint32_t bFragOff =
        ((wk + (lane & 7) + ((lane >> 4) & 1) * 8) * ASTRIDE +
         ((lane >> 3) & 1) * 8) * 2;
    const uint32_t T16 = 16 * ASTRIDE * 2;

    __half* Cp = At + ((size_t)bh << 20);
    const int g = lane >> 2, tg = (lane & 3) * 2;

    issueK(0, 0);

    for (int c = 0; c < 8; ++c) {
        if (c + 1 < 8) {
            issueK(c + 1, (c + 1) & 1);
            CP_WAIT(1);
        } else {
            CP_WAIT(0);
        }
        __syncthreads();

        float acc[2][4][4] = {};
        const uint32_t kbase = smemU + SCK_BASE + (c & 1) * SCK_STAGE;
        const uint32_t aH = smemU + SCQ_H + aFragOff;
        const uint32_t aL = smemU + SCQ_L + aFragOff;
        const uint32_t bH = kbase + bFragOff;
        const uint32_t bL = kbase + SCK_KL + bFragOff;

        // frag buffers: [buf][plane 0=H,1=L][tile/grp 0,1][4]
        uint32_t aF[2][2][2][4], bF[2][2][2][4];
        auto ldf = [&](int k16, int buf) {
            const uint32_t ko = (uint32_t)k16 * 32;
            LDSM4(aF[buf][0][0], aH + ko);
            LDSM4(aF[buf][0][1], aH + T16 + ko);
            LDSM4(aF[buf][1][0], aL + ko);
            LDSM4(aF[buf][1][1], aL + T16 + ko);
            LDSM4(bF[buf][0][0], bH + ko);
            LDSM4(bF[buf][0][1], bH + T16 + ko);
            LDSM4(bF[buf][1][0], bL + ko);
            LDSM4(bF[buf][1][1], bL + T16 + ko);
        };
        ldf(0, 0);
#pragma unroll
        for (int k16 = 0; k16 < 4; ++k16) {
            if (k16 < 3) ldf(k16 + 1, (k16 + 1) & 1);
            const int bu = k16 & 1;
#pragma unroll
            for (int mt = 0; mt < 2; ++mt)
#pragma unroll
                for (int grp = 0; grp < 2; ++grp)
#pragma unroll
                    for (int hf = 0; hf < 2; ++hf) {
                        float* a4 = acc[mt][grp * 2 + hf];
                        mma16816(a4, aF[bu][0][mt], bF[bu][0][grp] + 2 * hf);
                        mma16816(a4, aF[bu][1][mt], bF[bu][0][grp] + 2 * hf);
                        mma16816(a4, aF[bu][0][mt], bF[bu][1][grp] + 2 * hf);
                    }
        }

        // write 64 x 128 fp16 tile for this chunk
#pragma unroll
        for (int mt = 0; mt < 2; ++mt) {
            const int r0 = q0 + wq + mt * 16 + g;
#pragma unroll
            for (int nj = 0; nj < 4; ++nj) {
                const int col = c * 128 + wk + nj * 8 + tg;
                __half2 lo = __floats2half2_rn(acc[mt][nj][0] * 0.125f,
                                               acc[mt][nj][1] * 0.125f);
                __half2 hi = __floats2half2_rn(acc[mt][nj][2] * 0.125f,
                                               acc[mt][nj][3] * 0.125f);
                *(__half2*)&Cp[(size_t)r0 * 1024 + col] = lo;
                *(__half2*)&Cp[(size_t)(r0 + 8) * 1024 + col] = hi;
            }
        }
        __syncthreads();
    }
}

// ---------------------------------------------------------------------------
// fused softmax / z / masks / stats; reads fp16 At; emits (t-1) bf16 hi/lo
// ---------------------------------------------------------------------------
__device__ __forceinline__ float warpMaxF(float v) {
#pragma unroll
    for (int o = 16; o; o >>= 1) v = fmaxf(v, __shfl_xor_sync(0xffffffffu, v, o));
    return v;
}
__device__ __forceinline__ float warpSumF(float v) {
#pragma unroll
    for (int o = 16; o; o >>= 1) v += __shfl_xor_sync(0xffffffffu, v, o);
    return v;
}

__global__ __launch_bounds__(NT)
void fused_sm_kernel(const __half* __restrict__ At,
                     const float* __restrict__ cw,
                     const float* __restrict__ cbp,
                     unsigned char* __restrict__ maskbuf,
                     float* __restrict__ stats,
                     __nv_bfloat16* __restrict__ tdh,
                     __nv_bfloat16* __restrict__ tdl)
{
    const int bq = blockIdx.x;
    const int b  = bq >> 10;
    const int q  = bq & 1023;
    const int tid  = threadIdx.x;
    const int lane = tid & 31, wid = tid >> 5;

    __shared__ float red[16][8];
    __shared__ float fin[16];

    const float cb = cbp[0];
    const size_t rowbase = ((size_t)q << 10) + (size_t)tid * 4;

    float a[8][4];
    float lm[8];
#pragma unroll
    for (int h = 0; h < 8; ++h) {
        uint2 u = *(const uint2*)(At + (size_t)(b * 8 + h) * 1048576 + rowbase);
        float2 f0 = __half22float2(*(__half2*)&u.x);
        float2 f1 = __half22float2(*(__half2*)&u.y);
        a[h][0] = f0.x; a[h][1] = f0.y; a[h][2] = f1.x; a[h][3] = f1.y;
        lm[h] = fmaxf(fmaxf(a[h][0], a[h][1]), fmaxf(a[h][2], a[h][3]));
    }
#pragma unroll
    for (int h = 0; h < 8; ++h) {
        float w = warpMaxF(lm[h]);
        if (lane == 0) red[h][wid] = w;
    }
    __syncthreads();
    if (tid < 8) {
        float m = red[tid][0];
#pragma unroll
        for (int i = 1; i < 8; ++i) m = fmaxf(m, red[tid][i]);
        fin[tid] = m;
    }
    __syncthreads();
    float ls[8];
#pragma unroll
    for (int h = 0; h < 8; ++h) {
        float m = fin[h];
        float s = 0.f;
#pragma unroll
        for (int j = 0; j < 4; ++j) {
            a[h][j] = __expf(a[h][j] - m);
            s += a[h][j];
        }
        ls[h] = s;
    }
    __syncthreads();
#pragma unroll
    for (int h = 0; h < 8; ++h) {
        float w = warpSumF(ls[h]);
        if (lane == 0) red[h][wid] = w;
    }
    __syncthreads();
    if (tid < 8) {
        float s = red[tid][0];
#pragma unroll
        for (int i = 1; i < 8; ++i) s += red[tid][i];
        fin[tid] = 1.0f / s;
    }
    __syncthreads();

    float zacc[4] = {cb, cb, cb, cb};
#pragma unroll
    for (int h = 0; h < 8; ++h) {
        float inv = fin[h];
        float w   = cw[h];
#pragma unroll
        for (int j = 0; j < 4; ++j) {
            a[h][j] *= inv;
            zacc[j] = fmaf(a[h][j], w, zacc[j]);
        }
    }
    unsigned mby[4];
#pragma unroll
    for (int j = 0; j < 4; ++j) {
        unsigned mf = (zacc[j] <= 0.f) ? 1u : 0u;
        unsigned mr = (zacc[j] >= 0.f) ? 2u : 0u;
        mby[j] = mf | mr;
    }

    float lsf[8], lsr[8];
#pragma unroll
    for (int h = 0; h < 8; ++h) {
        float sf = 0.f, sr = 0.f;
#pragma unroll
        for (int j = 0; j < 4; ++j) {
            float t = __expf(a[h][j]);
            a[h][j] = t;
            sf += (mby[j] & 1u) ? t : 1.0f;
            sr += (mby[j] & 2u) ? t : 1.0f;
        }
        lsf[h] = sf; lsr[h] = sr;
    }
    __syncthreads();
#pragma unroll
    for (int h = 0; h < 8; ++h) {
        float w = warpSumF(lsf[h]);
        if (lane == 0) red[h][wid] = w;
        w = warpSumF(lsr[h]);
        if (lane == 0) red[8 + h][wid] = w;
    }
    __syncthreads();
    if (tid < 16) {
        float s = red[tid][0];
#pragma unroll
        for (int i = 1; i < 8; ++i) s += red[tid][i];
        float inv = 1.0f / s;
        int h = tid & 7;
        int row = (b * 8 + h) * 1024 + q;
        if (tid < 8) stats[row] = inv;
        else         stats[32768 + row] = inv;
    }

#pragma unroll
    for (int h = 0; h < 8; ++h) {
        size_t o = (size_t)(b * 8 + h) * 1048576 + rowbase;
        split2w(a[h][0] - 1.0f, a[h][1] - 1.0f, tdh + o, tdl + o);
        split2w(a[h][2] - 1.0f, a[h][3] - 1.0f, tdh + o + 2, tdl + o + 2);
    }
    uchar4 m4 = {(unsigned char)mby[0], (unsigned char)mby[1],
                 (unsigned char)mby[2], (unsigned char)mby[3]};
    *(uchar4*)(maskbuf + (size_t)bq * 1024 + tid * 4) = m4;
}

// ---------------------------------------------------------------------------
// colsum[bh][d] = sum_k (vh+vl)[b,k,h*64+d]
// ---------------------------------------------------------------------------
__global__ __launch_bounds__(NT)
void colsum_kernel(const __nv_bfloat16* __restrict__ vh,
                   const __nv_bfloat16* __restrict__ vl,
                   float* __restrict__ cs)
{
    const int bh = blockIdx.x, b = bh >> 3, h = bh & 7;
    const int tid = threadIdx.x;
    const int d = tid & 63, part = tid >> 6;
    __shared__ float red[4][64];
    const __nv_bfloat16* p1 = vh + ((size_t)(b * 1024 + part * 256)) * 512 + h * 64 + d;
    const __nv_bfloat16* p2 = vl + ((size_t)(b * 1024 + part * 256)) * 512 + h * 64 + d;
    float s = 0.f;
    for (int k = 0; k < 256; ++k)
        s += __bfloat162float(p1[(size_t)k * 512]) + __bfloat162float(p2[(size_t)k * 512]);
    red[part][d] = s;
    __syncthreads();
    if (tid < 64)
        cs[bh * 64 + tid] = red[0][tid] + red[1][tid] + red[2][tid] + red[3][tid];
}

// ---------------------------------------------------------------------------
// av (HMMA): per (b,h), q-tile 64.  Pipelined v-fragment loads.
// ---------------------------------------------------------------------------
__global__ __launch_bounds__(NT)
void av_hmma_kernel(const __nv_bfloat16* __restrict__ tdh,
                    const __nv_bfloat16* __restrict__ tdl,
                    const unsigned char* __restrict__ maskb,
                    const float* __restrict__ stats,
                    const float* __restrict__ colsum,
                    const __nv_bfloat16* __restrict__ vh,
                    const __nv_bfloat16* __restrict__ vl,
                    __nv_bfloat16* __restrict__ Tfh, __nv_bfloat16* __restrict__ Tfl,
                    __nv_bfloat16* __restrict__ Trh, __nv_bfloat16* __restrict__ Trl)
{
    extern __shared__ __align__(16) __nv_bfloat16 smem[];
    const uint32_t smemU = (uint32_t)__cvta_generic_to_shared(smem);
    const int bh = blockIdx.y, b = bh >> 3, h = bh & 7;
    const int q0 = blockIdx.x * 64;
    const int tid = threadIdx.x, lane = tid & 31, wid = tid >> 5;
    const int branch = wid >> 2;
    const int wq = (wid & 3) * 16;

    const int row = tid >> 2, seg = (tid & 3) * 16;

    const __nv_bfloat16* thp = tdh + (size_t)bh * 1048576 + (size_t)(q0 + row) * 1024 + seg;
    const __nv_bfloat16* tlp = tdl + (size_t)bh * 1048576 + (size_t)(q0 + row) * 1024 + seg;
    const unsigned char* mp  = maskb + ((size_t)(b * 1024 + q0 + row)) * 1024 + seg;
    const __nv_bfloat16* vhp = vh + ((size_t)(b * 1024 + row)) * 512 + h * 64 + seg;
    const __nv_bfloat16* vlp = vl + ((size_t)(b * 1024 + row)) * 512 + h * 64 + seg;

    uint4 thR[2], tlR[2], mkR;
    auto loadA = [&](int c) {
        const int k0 = c * 64;
        thR[0] = *(const uint4*)(thp + k0);
        thR[1] = *(const uint4*)(thp + k0 + 8);
        tlR[0] = *(const uint4*)(tlp + k0);
        tlR[1] = *(const uint4*)(tlp + k0 + 8);
        mkR    = *(const uint4*)(mp + k0);
    };
    auto issueV = [&](int c, int buf) {
        const size_t ko = (size_t)c * 64 * 512;
        const uint32_t base = smemU + buf * (AV_STAGE * 2) + (row * ASTRIDE + seg) * 2;
        cpa16(base + AV_VH * 2,      vhp + ko);
        cpa16(base + AV_VH * 2 + 16, vhp + ko + 8);
        cpa16(base + AV_VL * 2,      vlp + ko);
        cpa16(base + AV_VL * 2 + 16, vlp + ko + 8);
        CP_COMMIT();
    };
    auto selstore = [&](int buf) {
        const uint32_t* thw = (const uint32_t*)thR;
        const uint32_t* tlw = (const uint32_t*)tlR;
        uint32_t mkw[4] = {mkR.x, mkR.y, mkR.z, mkR.w};
        uint32_t afh[8], afl[8], arh[8], arl[8];
#pragma unroll
        for (int i = 0; i < 8; ++i) {
            uint32_t mw = mkw[i >> 1];
            uint32_t sh = (i & 1) * 16;
            uint32_t m0 = (mw >> sh) & 0xFFu;
            uint32_t m1 = (mw >> (sh + 8)) & 0xFFu;
            uint32_t sF = ((m0 & 1u) ? 0x0000FFFFu : 0u) | ((m1 & 1u) ? 0xFFFF0000u : 0u);
            uint32_t sR = ((m0 & 2u) ? 0x0000FFFFu : 0u) | ((m1 & 2u) ? 0xFFFF0000u : 0u);
            afh[i] = thw[i] & sF;  arh[i] = thw[i] & sR;
            afl[i] = tlw[i] & sF;  arl[i] = tlw[i] & sR;
        }
        const uint32_t base = smemU + buf * (AV_STAGE * 2) + (row * ASTRIDE + seg) * 2;
        STS128(base + AV_AFH * 2,      afh[0], afh[1], afh[2], afh[3]);
        STS128(base + AV_AFH * 2 + 16, afh[4], afh[5], afh[6], afh[7]);
        STS128(base + AV_AFL * 2,      afl[0], afl[1], afl[2], afl[3]);
        STS128(base + AV_AFL * 2 + 16, afl[4], afl[5], afl[6], afl[7]);
        STS128(base + AV_ARH * 2,      arh[0], arh[1], arh[2], arh[3]);
        STS128(base + AV_ARH * 2 + 16, arh[4], arh[5], arh[6], arh[7]);
        STS128(base + AV_ARL * 2,      arl[0], arl[1], arl[2], arl[3]);
        STS128(base + AV_ARL * 2 + 16, arl[4], arl[5], arl[6], arl[7]);
    };

    float acc[8][4] = {};
    const uint32_t aOffH = (branch ? AV_ARH : AV_AFH) * 2 +
        ((wq + (lane & 15)) * ASTRIDE + ((lane >> 4) & 1) * 8) * 2;
    const uint32_t aOffL = (branch ? AV_ARL : AV_AFL) * 2 +
        ((wq + (lane & 15)) * ASTRIDE + ((lane >> 4) & 1) * 8) * 2;
    const uint32_t vLaneOff = ((lane & 15) * ASTRIDE + ((lane >> 4) & 1) * 8) * 2;

    auto compute = [&](int buf) {
        const uint32_t sb = smemU + buf * (AV_STAGE * 2);
#pragma unroll
        for (int k16 = 0; k16 < 4; ++k16) {
            uint32_t ah[4], al[4];
            LDSM4(ah, sb + aOffH + k16 * 32);
            LDSM4(al, sb + aOffL + k16 * 32);
            const uint32_t vkb = sb + vLaneOff + k16 * 16 * ASTRIDE * 2;
            uint32_t fvh[2][4], fvl[2][4];
            LDSM4T(fvh[0], vkb + AV_VH * 2);
            LDSM4T(fvl[0], vkb + AV_VL * 2);
#pragma unroll
            for (int gg = 0; gg < 4; ++gg) {
                if (gg < 3) {
                    LDSM4T(fvh[(gg + 1) & 1], vkb + AV_VH * 2 + (gg + 1) * 32);
                    LDSM4T(fvl[(gg + 1) & 1], vkb + AV_VL * 2 + (gg + 1) * 32);
                }
                uint32_t* vh2 = fvh[gg & 1];
                uint32_t* vl2 = fvl[gg & 1];
                mma16816(acc[2 * gg],     ah, vh2);
                mma16816(acc[2 * gg],     ah, vl2);
                mma16816(acc[2 * gg],     al, vh2);
                mma16816(acc[2 * gg + 1], ah, vh2 + 2);
                mma16816(acc[2 * gg + 1], ah, vl2 + 2);
                mma16816(acc[2 * gg + 1], al, vh2 + 2);
            }
        }
    };

    loadA(0);
    issueV(0, 0);
    selstore(0);
    CP_WAIT(0);
    __syncthreads();

    for (int c = 0; c < 16; ++c) {
        const int cur = c & 1;
        const bool more = (c + 1) < 16;
        if (more) { issueV(c + 1, cur ^ 1); loadA(c + 1); }
        compute(cur);
        __syncthreads();
        if (more) {
            selstore(cur ^ 1);
            CP_WAIT(0);
            __syncthreads();
        }
    }

    const int g = lane >> 2, tg = (lane & 3) * 2;
    const int q1 = q0 + wq + g, q2 = q1 + 8;
    const int srow = (branch ? 32768 : 0) + bh * 1024;
    const float rs1 = stats[srow + q1];
    const float rs2 = stats[srow + q2];
    __nv_bfloat16* outH = branch ? Trh : Tfh;
    __nv_bfloat16* outL = branch ? Trl : Tfl;
#pragma unroll
    for (int n = 0; n < 8; ++n) {
        const int d = n * 8 + tg;
        const float cs0 = colsum[bh * 64 + d];
        const float cs1 = colsum[bh * 64 + d + 1];
        const size_t o1 = (size_t)(b * 1024 + q1) * 512 + h * 64 + d;
        const size_t o2 = (size_t)(b * 1024 + q2) * 512 + h * 64 + d;
        split2w((acc[n][0] + cs0) * rs1, (acc[n][1] + cs1) * rs1, outH + o1, outL + o1);
        split2w((acc[n][2] + cs0) * rs2, (acc[n][3] + cs1) * rs2, outH + o2, outL + o2);
    }
}

// ---------------------------------------------------------------------------
__global__ __launch_bounds__(NT)
void combine_kernel(const float* __restrict__ Ff, const float* __restrict__ Gf,
                    const float* __restrict__ Fr, const float* __restrict__ Gr,
                    float* __restrict__ out)
{
    const size_t i4 = (size_t)blockIdx.x * NT + threadIdx.x;
    float4 ff = ((const float4*)Ff)[i4];
    float4 gf = ((const float4*)Gf)[i4];
    float4 fr = ((const float4*)Fr)[i4];
    float4 gr = ((const float4*)Gr)[i4];

    float ffv[4] = {ff.x, ff.y, ff.z, ff.w};
    float gfv[4] = {gf.x, gf.y, gf.z, gf.w};
    float frv[4] = {fr.x, fr.y, fr.z, fr.w};
    float grv[4] = {gr.x, gr.y, gr.z, gr.w};
    float ov[4];
#pragma unroll
    for (int j = 0; j < 4; ++j) {
        float sgf = 1.0f / (1.0f + __expf(-gfv[j]));
        float sgr = 1.0f / (1.0f + __expf(-grv[j]));
        float w   = 1.0f / (1.0f + __expf(sgr - sgf));
        ov[j] = ffv[j] * w + frv[j] * (1.0f - w);
    }
    float4 o = {ov[0], ov[1], ov[2], ov[3]};
    ((float4*)out)[i4] = o;
}

// ---------------------------------------------------------------------------
extern "C" void kernel_launch(void* const* d_in, const int* in_sizes, int n_in,
                              void* d_out, int out_size)
{
    const float* x   = (const float*)d_in[0];
    const float* Wq  = (const float*)d_in[1];
    const float* bq  = (const float*)d_in[2];
    const float* Wk  = (const float*)d_in[3];
    const float* bk  = (const float*)d_in[4];
    const float* Wv  = (const float*)d_in[5];
    const float* bv  = (const float*)d_in[6];
    const float* cw  = (const float*)d_in[7];
    const float* cb  = (const float*)d_in[8];
    const float* Wfh = (const float*)d_in[9];
    const float* bfh = (const float*)d_in[10];
    const float* Wfg = (const float*)d_in[11];
    const float* bfg = (const float*)d_in[12];
    const float* Wrh = (const float*)d_in[13];
    const float* brh = (const float*)d_in[14];
    const float* Wrg = (const float*)d_in[15];
    const float* brg = (const float*)d_in[16];
    float* out = (float*)d_out;

    float* s = nullptr;
    cudaGetSymbolAddress((void**)&s, g_scratch);
    __nv_bfloat16* bb = nullptr;
    cudaGetSymbolAddress((void**)&bb, g_bfbuf);

    float* Ff    = s + OFF_FF;
    float* Gf    = s + OFF_GF;
    float* Fr    = s + OFF_FR;
    float* Gr    = s + OFF_GR;
    unsigned char* maskb = (unsigned char*)(s + OFF_MB);
    float* stats = s + OFF_ST;
    float* csum  = s + OFF_CS;
    __half* At   = (__half*)(s + OFF_AT);

    __nv_bfloat16* xh  = bb + BX_H;
    __nv_bfloat16* xl  = bb + BX_L;
    __nv_bfloat16* tfh = bb + BTF_H;
    __nv_bfloat16* tfl = bb + BTF_L;
    __nv_bfloat16* trh = bb + BTR_H;
    __nv_bfloat16* trl = bb + BTR_L;
    __nv_bfloat16* wb  = bb + BW;
    __nv_bfloat16* qhb = bb + BQ_H;
    __nv_bfloat16* qlb = bb + BQ_L;
    __nv_bfloat16* khb = bb + BK_H;
    __nv_bfloat16* klb = bb + BK_L;
    __nv_bfloat16* vhb = bb + BV_H;
    __nv_bfloat16* vlb = bb + BV_L;
    __nv_bfloat16* tdh = bb + BT_H;
    __nv_bfloat16* tdl = bb + BT_L;

    cudaFuncSetAttribute(hmma_gemm_kernel,
                         cudaFuncAttributeMaxDynamicSharedMemorySize, HM_SMEM);
    cudaFuncSetAttribute(scores_hmma_kernel,
                         cudaFuncAttributeMaxDynamicSharedMemorySize, SC_SMEM);
    cudaFuncSetAttribute(av_hmma_kernel,
                         cudaFuncAttributeMaxDynamicSharedMemorySize, AV_SMEM);

    WPack wp;
    wp.w[0] = Wq;  wp.w[1] = Wk;  wp.w[2] = Wv;
    wp.w[3] = Wfh; wp.w[4] = Wfg; wp.w[5] = Wrh; wp.w[6] = Wrg;
    splitw_kernel<<<dim3(16, 16, 7), NT>>>(wp, wb);
    splitx_kernel<<<2048, NT>>>(x, xh, xl);

    GJobs qkv = {};
    qkv.j[0] = {xh, xl, wb + 0 * 524288, wb + 0 * 524288 + 262144, bq, nullptr, qhb, qlb, 1};
    qkv.j[1] = {xh, xl, wb + 1 * 524288, wb + 1 * 524288 + 262144, bk, nullptr, khb, klb, 1};
    qkv.j[2] = {xh, xl, wb + 2 * 524288, wb + 2 * 524288 + 262144, bv, nullptr, vhb, vlb, 1};
    hmma_gemm_kernel<<<dim3(8, 32, 3), NT, HM_SMEM>>>(qkv);

    scores_hmma_kernel<<<dim3(16, 32), NT, SC_SMEM>>>(qhb, qlb, khb, klb, At);
    fused_sm_kernel<<<4096, NT>>>(At, cw, cb, maskb, stats, tdh, tdl);
    colsum_kernel<<<32, NT>>>(vhb, vlb, csum);
    av_hmma_kernel<<<dim3(16, 32), NT, AV_SMEM>>>(tdh, tdl, maskb, stats, csum,
                                                  vhb, vlb, tfh, tfl, trh, trl);

    GJobs fin = {};
    fin.j[0] = {tfh, tfl, wb + 3 * 524288, wb + 3 * 524288 + 262144, bfh, Ff, nullptr, nullptr, 0};
    fin.j[1] = {tfh, tfl, wb + 4 * 524288, wb + 4 * 524288 + 262144, bfg, Gf, nullptr, nullptr, 0};
    fin.j[2] = {trh, trl, wb + 5 * 524288, wb + 5 * 524288 + 262144, brh, Fr, nullptr, nullptr, 0};
    fin.j[3] = {trh, trl, wb + 6 * 524288, wb + 6 * 524288 + 262144, brg, Gr, nullptr, nullptr, 0};
    hmma_gemm_kernel<<<dim3(8, 32, 4), NT, HM_SMEM>>>(fin);

    combine_kernel<<<2048, NT>>>(Ff, Gf, Fr, Gr, out);
}